// round 6
// baseline (speedup 1.0000x reference)
#include <cuda_runtime.h>
#include <math.h>

#define BB 4
#define TT 2048
#define EE 512
#define HH 8
#define DD 64
#define HIDD 4096
#define NROWS (BB*TT)            // 8192

// ---------------- scratch (static device globals; no runtime allocation) ----
__device__ float g_xn [NROWS*EE];        // LN1 output
__device__ float g_q  [NROWS*EE];        // [B,H,T,D]
__device__ float g_k  [NROWS*EE];
__device__ float g_v  [NROWS*EE];
__device__ float g_o  [NROWS*EE];        // attention out, [B,T,H*D]
__device__ float g_x2 [NROWS*EE];        // xn + mha
__device__ float g_xn2[NROWS*EE];        // LN2 output
__device__ float g_h1 [NROWS*HIDD];      // FFN hidden

// ---------------- LayerNorm: one block per row (E=512, 256 threads) ---------
__global__ __launch_bounds__(256) void ln_kernel(const float* __restrict__ x,
                                                 const float* __restrict__ g,
                                                 const float* __restrict__ b,
                                                 float* __restrict__ out) {
    const int row = blockIdx.x;
    const int tid = threadIdx.x;
    const float* xr = x + (size_t)row * EE;
    float v0 = xr[tid];
    float v1 = xr[tid + 256];
    float s  = v0 + v1;
    float ss = v0 * v0 + v1 * v1;
    #pragma unroll
    for (int off = 16; off; off >>= 1) {
        s  += __shfl_xor_sync(0xffffffffu, s,  off);
        ss += __shfl_xor_sync(0xffffffffu, ss, off);
    }
    __shared__ float sh_s[8], sh_ss[8];
    const int w = tid >> 5, ln = tid & 31;
    if (ln == 0) { sh_s[w] = s; sh_ss[w] = ss; }
    __syncthreads();
    float ts = 0.f, tss = 0.f;
    #pragma unroll
    for (int i = 0; i < 8; i++) { ts += sh_s[i]; tss += sh_ss[i]; }
    const float mean = ts * (1.0f / EE);
    const float var  = tss * (1.0f / EE) - mean * mean;
    const float inv  = rsqrtf(var + 1e-5f);
    float* orow = out + (size_t)row * EE;
    orow[tid]       = (v0 - mean) * inv * g[tid]       + b[tid];
    orow[tid + 256] = (v1 - mean) * inv * g[tid + 256] + b[tid + 256];
}

// ---------------- fused QKV projection -------------------------------------
// Per block: one (b,h), 64 query rows. C[64,64] x3 with shared A tile reuse.
__global__ __launch_bounds__(256) void qkv_kernel(const float* __restrict__ Wq,
                                                  const float* __restrict__ Wk,
                                                  const float* __restrict__ Wv) {
    __shared__ float As[16][68], Bq[16][68], Bk[16][68], Bv[16][68];
    const int t0 = blockIdx.x * 64;
    const int bh = blockIdx.y;
    const int b = bh >> 3, h = bh & 7;
    const float* A  = g_xn + ((size_t)b * TT + t0) * EE;
    const float* wq = Wq + (size_t)h * EE * DD;
    const float* wk = Wk + (size_t)h * EE * DD;
    const float* wv = Wv + (size_t)h * EE * DD;
    const int tid = threadIdx.x;
    const int tx = tid & 15, ty = tid >> 4;

    float aq[4][4] = {}, ak[4][4] = {}, av[4][4] = {};

    for (int k0 = 0; k0 < EE; k0 += 16) {
        #pragma unroll
        for (int it = 0; it < 4; it++) {
            int idx = tid + it * 256;
            int r = idx >> 4, kk = idx & 15;
            As[kk][r] = A[(size_t)r * EE + k0 + kk];
            int kb = idx >> 6, c = idx & 63;
            Bq[kb][c] = wq[(size_t)(k0 + kb) * DD + c];
            Bk[kb][c] = wk[(size_t)(k0 + kb) * DD + c];
            Bv[kb][c] = wv[(size_t)(k0 + kb) * DD + c];
        }
        __syncthreads();
        #pragma unroll
        for (int kk = 0; kk < 16; kk++) {
            float4 a4 = *(const float4*)&As[kk][ty * 4];
            float4 q4 = *(const float4*)&Bq[kk][tx * 4];
            float4 k4 = *(const float4*)&Bk[kk][tx * 4];
            float4 v4 = *(const float4*)&Bv[kk][tx * 4];
            float aa[4] = {a4.x, a4.y, a4.z, a4.w};
            float qc[4] = {q4.x, q4.y, q4.z, q4.w};
            float kc[4] = {k4.x, k4.y, k4.z, k4.w};
            float vc[4] = {v4.x, v4.y, v4.z, v4.w};
            #pragma unroll
            for (int i = 0; i < 4; i++)
                #pragma unroll
                for (int j = 0; j < 4; j++) {
                    aq[i][j] += aa[i] * qc[j];
                    ak[i][j] += aa[i] * kc[j];
                    av[i][j] += aa[i] * vc[j];
                }
        }
        __syncthreads();
    }

    float* qo = g_q + ((size_t)(b * HH + h) * TT + t0) * DD;
    float* ko = g_k + ((size_t)(b * HH + h) * TT + t0) * DD;
    float* vo = g_v + ((size_t)(b * HH + h) * TT + t0) * DD;
    #pragma unroll
    for (int i = 0; i < 4; i++)
        #pragma unroll
        for (int j = 0; j < 4; j++) {
            int off = (ty * 4 + i) * DD + tx * 4 + j;
            qo[off] = aq[i][j];
            ko[off] = ak[i][j];
            vo[off] = av[i][j];
        }
}

// ---------------- flash attention (causal, scale = T^-0.5) -----------------
__global__ __launch_bounds__(256) void attn_kernel() {
    extern __shared__ float sm[];
    float (*Qs)[68] = reinterpret_cast<float (*)[68]>(sm);
    float (*Ks)[68] = reinterpret_cast<float (*)[68]>(sm + 64 * 68);
    float (*Vs)[68] = reinterpret_cast<float (*)[68]>(sm + 2 * 64 * 68);
    float (*Ps)[68] = reinterpret_cast<float (*)[68]>(sm + 3 * 64 * 68);

    const int t0 = blockIdx.x * 64;
    const int bh = blockIdx.y;
    const int b = bh >> 3, h = bh & 7;
    const int tid = threadIdx.x;
    const int tx = tid & 15, ty = tid >> 4;

    const float* qp = g_q + ((size_t)(b * HH + h) * TT + t0) * DD;
    const float* kp = g_k + (size_t)(b * HH + h) * TT * DD;
    const float* vp = g_v + (size_t)(b * HH + h) * TT * DD;

    // 64x64 tile = 4096 floats = 1024 float4; 256 threads x 4 iters.
    #pragma unroll
    for (int it = 0; it < 4; it++) {
        int idx = tid + it * 256;          // 0..1023
        int r = idx >> 4, c4 = idx & 15;   // r 0..63, c4 0..15
        *(float4*)&Qs[r][c4 * 4] = *(const float4*)&qp[(size_t)r * DD + c4 * 4];
    }

    float m[4], l[4], o[4][4];
    #pragma unroll
    for (int i = 0; i < 4; i++) {
        m[i] = -1e30f; l[i] = 0.f;
        #pragma unroll
        for (int j = 0; j < 4; j++) o[i][j] = 0.f;
    }

    const float scale = 0.022097086912079608f;   // 2048^-0.5

    for (int s0 = 0; s0 <= t0; s0 += 64) {
        __syncthreads();   // protect Ks/Vs/Ps reuse (also orders Qs fill on iter 0)
        #pragma unroll
        for (int it = 0; it < 4; it++) {
            int idx = tid + it * 256;
            int r = idx >> 4, c4 = idx & 15;
            *(float4*)&Ks[r][c4 * 4] = *(const float4*)&kp[(size_t)(s0 + r) * DD + c4 * 4];
            *(float4*)&Vs[r][c4 * 4] = *(const float4*)&vp[(size_t)(s0 + r) * DD + c4 * 4];
        }
        __syncthreads();

        // S = Q @ K^T
        float s[4][4] = {};
        #pragma unroll
        for (int d4 = 0; d4 < 16; d4++) {
            float4 aa[4], bb[4];
            #pragma unroll
            for (int i = 0; i < 4; i++) aa[i] = *(const float4*)&Qs[ty * 4 + i][d4 * 4];
            #pragma unroll
            for (int j = 0; j < 4; j++) bb[j] = *(const float4*)&Ks[tx * 4 + j][d4 * 4];
            #pragma unroll
            for (int i = 0; i < 4; i++)
                #pragma unroll
                for (int j = 0; j < 4; j++)
                    s[i][j] += aa[i].x * bb[j].x + aa[i].y * bb[j].y +
                               aa[i].z * bb[j].z + aa[i].w * bb[j].w;
        }

        // scale + causal mask
        #pragma unroll
        for (int i = 0; i < 4; i++) {
            int t = t0 + ty * 4 + i;
            #pragma unroll
            for (int j = 0; j < 4; j++) {
                int kidx = s0 + tx * 4 + j;
                s[i][j] = (kidx <= t) ? s[i][j] * scale : -1e30f;
            }
        }

        // online softmax update
        #pragma unroll
        for (int i = 0; i < 4; i++) {
            float mb = fmaxf(fmaxf(s[i][0], s[i][1]), fmaxf(s[i][2], s[i][3]));
            #pragma unroll
            for (int off = 8; off; off >>= 1)
                mb = fmaxf(mb, __shfl_xor_sync(0xffffffffu, mb, off));
            float mn = fmaxf(m[i], mb);
            float alpha = __expf(m[i] - mn);
            float rs = 0.f;
            #pragma unroll
            for (int j = 0; j < 4; j++) { s[i][j] = __expf(s[i][j] - mn); rs += s[i][j]; }
            #pragma unroll
            for (int off = 8; off; off >>= 1)
                rs += __shfl_xor_sync(0xffffffffu, rs, off);
            l[i] = l[i] * alpha + rs;
            m[i] = mn;
            #pragma unroll
            for (int j = 0; j < 4; j++) o[i][j] *= alpha;
        }

        #pragma unroll
        for (int i = 0; i < 4; i++)
            #pragma unroll
            for (int j = 0; j < 4; j++)
                Ps[ty * 4 + i][tx * 4 + j] = s[i][j];
        __syncthreads();

        // O += P @ V
        #pragma unroll
        for (int k4 = 0; k4 < 16; k4++) {
            float4 pr[4], vr[4];
            #pragma unroll
            for (int i = 0; i < 4; i++) pr[i] = *(const float4*)&Ps[ty * 4 + i][k4 * 4];
            #pragma unroll
            for (int kc = 0; kc < 4; kc++) vr[kc] = *(const float4*)&Vs[k4 * 4 + kc][tx * 4];
            #pragma unroll
            for (int i = 0; i < 4; i++) {
                o[i][0] += pr[i].x * vr[0].x + pr[i].y * vr[1].x + pr[i].z * vr[2].x + pr[i].w * vr[3].x;
                o[i][1] += pr[i].x * vr[0].y + pr[i].y * vr[1].y + pr[i].z * vr[2].y + pr[i].w * vr[3].y;
                o[i][2] += pr[i].x * vr[0].z + pr[i].y * vr[1].z + pr[i].z * vr[2].z + pr[i].w * vr[3].z;
                o[i][3] += pr[i].x * vr[0].w + pr[i].y * vr[1].w + pr[i].z * vr[2].w + pr[i].w * vr[3].w;
            }
        }
    }

    // write o / l into [B,T,H*D]
    float* op = g_o + ((size_t)(b * TT + t0)) * EE + h * DD;
    #pragma unroll
    for (int i = 0; i < 4; i++) {
        float inv = 1.0f / l[i];
        #pragma unroll
        for (int j = 0; j < 4; j++)
            op[(size_t)(ty * 4 + i) * EE + tx * 4 + j] = o[i][j] * inv;
    }
}

// ---------------- generic 128x128x16 SGEMM with fused epilogue -------------
// C[M,N] = A[M,K] @ B[K,N] (+bias[N]) (relu) (+res[M,N]); all row-major.
template <bool HAS_BIAS, bool DO_RELU, bool HAS_RES>
__global__ __launch_bounds__(256) void gemm128(const float* __restrict__ A,
                                               const float* __restrict__ B,
                                               const float* __restrict__ bias,
                                               const float* __restrict__ res,
                                               float* __restrict__ C,
                                               int N, int K) {
    __shared__ float As[16][132];
    __shared__ float Bs[16][132];
    const int n0 = blockIdx.x * 128;
    const int m0 = blockIdx.y * 128;
    const int tid = threadIdx.x;
    const int tx = tid & 15, ty = tid >> 4;

    float acc[8][8] = {};
    const float* Ab = A + (size_t)m0 * K;

    for (int k0 = 0; k0 < K; k0 += 16) {
        #pragma unroll
        for (int it = 0; it < 8; it++) {
            int idx = tid + it * 256;
            int r = idx >> 4, kk = idx & 15;
            As[kk][r] = Ab[(size_t)r * K + k0 + kk];
            int kb = idx >> 7, c = idx & 127;
            Bs[kb][c] = B[(size_t)(k0 + kb) * N + n0 + c];
        }
        __syncthreads();
        #pragma unroll
        for (int kk = 0; kk < 16; kk++) {
            float4 a0 = *(const float4*)&As[kk][ty * 4];
            float4 a1 = *(const float4*)&As[kk][64 + ty * 4];
            float4 b0 = *(const float4*)&Bs[kk][tx * 4];
            float4 b1 = *(const float4*)&Bs[kk][64 + tx * 4];
            float aa[8] = {a0.x, a0.y, a0.z, a0.w, a1.x, a1.y, a1.z, a1.w};
            float bb[8] = {b0.x, b0.y, b0.z, b0.w, b1.x, b1.y, b1.z, b1.w};
            #pragma unroll
            for (int i = 0; i < 8; i++)
                #pragma unroll
                for (int j = 0; j < 8; j++)
                    acc[i][j] += aa[i] * bb[j];
        }
        __syncthreads();
    }

    #pragma unroll
    for (int i = 0; i < 8; i++) {
        int r = m0 + ((i >> 2) << 6) + ty * 4 + (i & 3);
        #pragma unroll
        for (int j = 0; j < 8; j++) {
            int c = n0 + ((j >> 2) << 6) + tx * 4 + (j & 3);
            float v = acc[i][j];
            if (HAS_BIAS) v += bias[c];
            if (DO_RELU)  v = fmaxf(v, 0.0f);
            if (HAS_RES)  v += res[(size_t)r * N + c];
            C[(size_t)r * N + c] = v;
        }
    }
}

// ---------------- launch ----------------------------------------------------
extern "C" void kernel_launch(void* const* d_in, const int* in_sizes, int n_in,
                              void* d_out, int out_size) {
    const float* x   = (const float*)d_in[0];
    const float* Wq  = (const float*)d_in[1];
    const float* Wk  = (const float*)d_in[2];
    const float* Wv  = (const float*)d_in[3];
    const float* Wo  = (const float*)d_in[4];
    const float* bo  = (const float*)d_in[5];
    const float* W1  = (const float*)d_in[6];
    const float* b1  = (const float*)d_in[7];
    const float* W2  = (const float*)d_in[8];
    const float* b2  = (const float*)d_in[9];
    const float* g1  = (const float*)d_in[10];
    const float* be1 = (const float*)d_in[11];
    const float* g2  = (const float*)d_in[12];
    const float* be2 = (const float*)d_in[13];
    float* out = (float*)d_out;
    (void)in_sizes; (void)n_in; (void)out_size;

    float *xn, *o, *x2, *xn2, *h1;
    cudaGetSymbolAddress((void**)&xn,  g_xn);
    cudaGetSymbolAddress((void**)&o,   g_o);
    cudaGetSymbolAddress((void**)&x2,  g_x2);
    cudaGetSymbolAddress((void**)&xn2, g_xn2);
    cudaGetSymbolAddress((void**)&h1,  g_h1);

    const int attn_smem = 4 * 64 * 68 * (int)sizeof(float);   // 69632 B
    cudaFuncSetAttribute(attn_kernel,
                         cudaFuncAttributeMaxDynamicSharedMemorySize, attn_smem);

    // 1. xn = LN1(x)
    ln_kernel<<<NROWS, 256>>>(x, g1, be1, xn);
    // 2. q,k,v
    qkv_kernel<<<dim3(TT / 64, BB * HH), 256>>>(Wq, Wk, Wv);
    // 3. causal attention -> g_o  [B,T,H*D]
    attn_kernel<<<dim3(TT / 64, BB * HH), 256, attn_smem>>>();
    // 4. x2 = xn + o @ Wo + bo
    gemm128<true, false, true><<<dim3(EE / 128, NROWS / 128), 256>>>(o, Wo, bo, xn, x2, EE, EE);
    // 5. xn2 = LN2(x2)
    ln_kernel<<<NROWS, 256>>>(x2, g2, be2, xn2);
    // 6. h1 = relu(xn2 @ W1 + b1)
    gemm128<true, true, false><<<dim3(HIDD / 128, NROWS / 128), 256>>>(xn2, W1, b1, nullptr, h1, HIDD, EE);
    // 7. out = xn2 + h1 @ W2 + b2
    gemm128<true, false, true><<<dim3(EE / 128, NROWS / 128), 256>>>(h1, W2, b2, xn2, out, EE, HIDD);
}

// round 10
// speedup vs baseline: 1.6428x; 1.6428x over previous
#include <cuda_runtime.h>
#include <cuda_bf16.h>
#include <stdint.h>
#include <math.h>

#define BB 4
#define TT 2048
#define EE 512
#define HH 8
#define DD 64
#define HIDD 4096
#define NROWS (BB*TT)            // 8192

// ---------------- scratch (static device globals; no runtime allocation) ----
__device__ float g_xn [NROWS*EE];        // LN1 output (fp32, feeds QKV + residual)
__device__ float g_q  [NROWS*EE];        // [B,H,T,D]
__device__ float g_k  [NROWS*EE];
__device__ float g_v  [NROWS*EE];
__device__ float g_x2 [NROWS*EE];        // xn + mha
__device__ float g_xn2[NROWS*EE];        // LN2 output fp32 (residual for step 7)

// bf16 hi/lo split pairs (fp32 ~= hi + lo)
__device__ __align__(16) __nv_bfloat16 g_ohi [NROWS*EE],  g_olo [NROWS*EE];   // attn out
__device__ __align__(16) __nv_bfloat16 g_x2hi[NROWS*EE],  g_x2lo[NROWS*EE];   // xn2 pair
__device__ __align__(16) __nv_bfloat16 g_h1hi[NROWS*HIDD], g_h1lo[NROWS*HIDD]; // FFN hidden
__device__ __align__(16) __nv_bfloat16 g_wothi[EE*EE],   g_wotlo[EE*EE];      // Wo^T [E, HD]
__device__ __align__(16) __nv_bfloat16 g_w1thi[HIDD*EE], g_w1tlo[HIDD*EE];    // W1^T [HID, E]
__device__ __align__(16) __nv_bfloat16 g_w2thi[EE*HIDD], g_w2tlo[EE*HIDD];    // W2^T [E, HID]

// ---------------- mma.sync helpers (baseline PTX, no sm_103a features) ------
static __device__ __forceinline__ uint32_t smem_u32(const void* p) {
    uint32_t a;
    asm("{ .reg .u64 t; cvta.to.shared.u64 t, %1; cvt.u32.u64 %0, t; }" : "=r"(a) : "l"(p));
    return a;
}
static __device__ __forceinline__ void ldm_x4(uint32_t* r, uint32_t addr) {
    asm volatile("ldmatrix.sync.aligned.m8n8.x4.shared.b16 {%0,%1,%2,%3}, [%4];"
                 : "=r"(r[0]), "=r"(r[1]), "=r"(r[2]), "=r"(r[3]) : "r"(addr));
}
static __device__ __forceinline__ void ldm_x2(uint32_t* r, uint32_t addr) {
    asm volatile("ldmatrix.sync.aligned.m8n8.x2.shared.b16 {%0,%1}, [%2];"
                 : "=r"(r[0]), "=r"(r[1]) : "r"(addr));
}
static __device__ __forceinline__ void mma16816(float* c, const uint32_t* a, const uint32_t* b) {
    asm volatile("mma.sync.aligned.m16n8k16.row.col.f32.bf16.bf16.f32 "
                 "{%0,%1,%2,%3}, {%4,%5,%6,%7}, {%8,%9}, {%0,%1,%2,%3};"
                 : "+f"(c[0]), "+f"(c[1]), "+f"(c[2]), "+f"(c[3])
                 : "r"(a[0]), "r"(a[1]), "r"(a[2]), "r"(a[3]), "r"(b[0]), "r"(b[1]));
}

// ---------------- LayerNorm (optionally emits bf16 hi/lo pair) --------------
template <bool PAIR>
__global__ __launch_bounds__(256) void ln_kernel(const float* __restrict__ x,
                                                 const float* __restrict__ g,
                                                 const float* __restrict__ b,
                                                 float* __restrict__ out,
                                                 __nv_bfloat16* __restrict__ ohi,
                                                 __nv_bfloat16* __restrict__ olo) {
    const int row = blockIdx.x;
    const int tid = threadIdx.x;
    const float* xr = x + (size_t)row * EE;
    float v0 = xr[tid];
    float v1 = xr[tid + 256];
    float s  = v0 + v1;
    float ss = v0 * v0 + v1 * v1;
    #pragma unroll
    for (int off = 16; off; off >>= 1) {
        s  += __shfl_xor_sync(0xffffffffu, s,  off);
        ss += __shfl_xor_sync(0xffffffffu, ss, off);
    }
    __shared__ float sh_s[8], sh_ss[8];
    const int w = tid >> 5, ln = tid & 31;
    if (ln == 0) { sh_s[w] = s; sh_ss[w] = ss; }
    __syncthreads();
    float ts = 0.f, tss = 0.f;
    #pragma unroll
    for (int i = 0; i < 8; i++) { ts += sh_s[i]; tss += sh_ss[i]; }
    const float mean = ts * (1.0f / EE);
    const float var  = tss * (1.0f / EE) - mean * mean;
    const float inv  = rsqrtf(var + 1e-5f);
    float* orow = out + (size_t)row * EE;
    float y0 = (v0 - mean) * inv * g[tid]       + b[tid];
    float y1 = (v1 - mean) * inv * g[tid + 256] + b[tid + 256];
    orow[tid]       = y0;
    orow[tid + 256] = y1;
    if (PAIR) {
        __nv_bfloat16 h0 = __float2bfloat16(y0);
        __nv_bfloat16 h1 = __float2bfloat16(y1);
        ohi[(size_t)row * EE + tid]       = h0;
        ohi[(size_t)row * EE + tid + 256] = h1;
        olo[(size_t)row * EE + tid]       = __float2bfloat16(y0 - __bfloat162float(h0));
        olo[(size_t)row * EE + tid + 256] = __float2bfloat16(y1 - __bfloat162float(h1));
    }
}

// ---------------- weight transpose + hi/lo split ----------------------------
// W [K, N] fp32 row-major -> T_hi/T_lo [N, K] bf16.
__global__ __launch_bounds__(256) void wsplit_kernel(const float* __restrict__ W,
                                                     __nv_bfloat16* __restrict__ Thi,
                                                     __nv_bfloat16* __restrict__ Tlo,
                                                     int K, int N) {
    __shared__ float t[32][33];
    const int n0 = blockIdx.x * 32, k0 = blockIdx.y * 32;
    const int tx = threadIdx.x & 31, ty = threadIdx.x >> 5;   // 32 x 8
    #pragma unroll
    for (int i = ty; i < 32; i += 8)
        t[i][tx] = W[(size_t)(k0 + i) * N + n0 + tx];
    __syncthreads();
    #pragma unroll
    for (int i = ty; i < 32; i += 8) {
        float v = t[tx][i];                     // W[k0+tx][n0+i]
        __nv_bfloat16 h = __float2bfloat16(v);
        Thi[(size_t)(n0 + i) * K + k0 + tx] = h;
        Tlo[(size_t)(n0 + i) * K + k0 + tx] = __float2bfloat16(v - __bfloat162float(h));
    }
}

// ---------------- fused QKV projection (SIMT, unchanged) --------------------
__global__ __launch_bounds__(256) void qkv_kernel(const float* __restrict__ Wq,
                                                  const float* __restrict__ Wk,
                                                  const float* __restrict__ Wv) {
    __shared__ float As[16][68], Bq[16][68], Bk[16][68], Bv[16][68];
    const int t0 = blockIdx.x * 64;
    const int bh = blockIdx.y;
    const int b = bh >> 3, h = bh & 7;
    const float* A  = g_xn + ((size_t)b * TT + t0) * EE;
    const float* wq = Wq + (size_t)h * EE * DD;
    const float* wk = Wk + (size_t)h * EE * DD;
    const float* wv = Wv + (size_t)h * EE * DD;
    const int tid = threadIdx.x;
    const int tx = tid & 15, ty = tid >> 4;

    float aq[4][4] = {}, ak[4][4] = {}, av[4][4] = {};

    for (int k0 = 0; k0 < EE; k0 += 16) {
        #pragma unroll
        for (int it = 0; it < 4; it++) {
            int idx = tid + it * 256;
            int r = idx >> 4, kk = idx & 15;
            As[kk][r] = A[(size_t)r * EE + k0 + kk];
            int kb = idx >> 6, c = idx & 63;
            Bq[kb][c] = wq[(size_t)(k0 + kb) * DD + c];
            Bk[kb][c] = wk[(size_t)(k0 + kb) * DD + c];
            Bv[kb][c] = wv[(size_t)(k0 + kb) * DD + c];
        }
        __syncthreads();
        #pragma unroll
        for (int kk = 0; kk < 16; kk++) {
            float4 a4 = *(const float4*)&As[kk][ty * 4];
            float4 q4 = *(const float4*)&Bq[kk][tx * 4];
            float4 k4 = *(const float4*)&Bk[kk][tx * 4];
            float4 v4 = *(const float4*)&Bv[kk][tx * 4];
            float aa[4] = {a4.x, a4.y, a4.z, a4.w};
            float qc[4] = {q4.x, q4.y, q4.z, q4.w};
            float kc[4] = {k4.x, k4.y, k4.z, k4.w};
            float vc[4] = {v4.x, v4.y, v4.z, v4.w};
            #pragma unroll
            for (int i = 0; i < 4; i++)
                #pragma unroll
                for (int j = 0; j < 4; j++) {
                    aq[i][j] += aa[i] * qc[j];
                    ak[i][j] += aa[i] * kc[j];
                    av[i][j] += aa[i] * vc[j];
                }
        }
        __syncthreads();
    }

    float* qo = g_q + ((size_t)(b * HH + h) * TT + t0) * DD;
    float* ko = g_k + ((size_t)(b * HH + h) * TT + t0) * DD;
    float* vo = g_v + ((size_t)(b * HH + h) * TT + t0) * DD;
    #pragma unroll
    for (int i = 0; i < 4; i++)
        #pragma unroll
        for (int j = 0; j < 4; j++) {
            int off = (ty * 4 + i) * DD + tx * 4 + j;
            qo[off] = aq[i][j];
            ko[off] = ak[i][j];
            vo[off] = av[i][j];
        }
}

// ---------------- flash attention; epilogue emits bf16 hi/lo ----------------
__global__ __launch_bounds__(256) void attn_kernel() {
    extern __shared__ float sm[];
    float (*Qs)[68] = reinterpret_cast<float (*)[68]>(sm);
    float (*Ks)[68] = reinterpret_cast<float (*)[68]>(sm + 64 * 68);
    float (*Vs)[68] = reinterpret_cast<float (*)[68]>(sm + 2 * 64 * 68);
    float (*Ps)[68] = reinterpret_cast<float (*)[68]>(sm + 3 * 64 * 68);

    const int t0 = blockIdx.x * 64;
    const int bh = blockIdx.y;
    const int b = bh >> 3, h = bh & 7;
    const int tid = threadIdx.x;
    const int tx = tid & 15, ty = tid >> 4;

    const float* qp = g_q + ((size_t)(b * HH + h) * TT + t0) * DD;
    const float* kp = g_k + (size_t)(b * HH + h) * TT * DD;
    const float* vp = g_v + (size_t)(b * HH + h) * TT * DD;

    #pragma unroll
    for (int it = 0; it < 4; it++) {
        int idx = tid + it * 256;
        int r = idx >> 4, c4 = idx & 15;
        *(float4*)&Qs[r][c4 * 4] = *(const float4*)&qp[(size_t)r * DD + c4 * 4];
    }

    float m[4], l[4], o[4][4];
    #pragma unroll
    for (int i = 0; i < 4; i++) {
        m[i] = -1e30f; l[i] = 0.f;
        #pragma unroll
        for (int j = 0; j < 4; j++) o[i][j] = 0.f;
    }

    const float scale = 0.022097086912079608f;   // 2048^-0.5

    for (int s0 = 0; s0 <= t0; s0 += 64) {
        __syncthreads();
        #pragma unroll
        for (int it = 0; it < 4; it++) {
            int idx = tid + it * 256;
            int r = idx >> 4, c4 = idx & 15;
            *(float4*)&Ks[r][c4 * 4] = *(const float4*)&kp[(size_t)(s0 + r) * DD + c4 * 4];
            *(float4*)&Vs[r][c4 * 4] = *(const float4*)&vp[(size_t)(s0 + r) * DD + c4 * 4];
        }
        __syncthreads();

        float s[4][4] = {};
        #pragma unroll
        for (int d4 = 0; d4 < 16; d4++) {
            float4 aa[4], bb[4];
            #pragma unroll
            for (int i = 0; i < 4; i++) aa[i] = *(const float4*)&Qs[ty * 4 + i][d4 * 4];
            #pragma unroll
            for (int j = 0; j < 4; j++) bb[j] = *(const float4*)&Ks[tx * 4 + j][d4 * 4];
            #pragma unroll
            for (int i = 0; i < 4; i++)
                #pragma unroll
                for (int j = 0; j < 4; j++)
                    s[i][j] += aa[i].x * bb[j].x + aa[i].y * bb[j].y +
                               aa[i].z * bb[j].z + aa[i].w * bb[j].w;
        }

        #pragma unroll
        for (int i = 0; i < 4; i++) {
            int t = t0 + ty * 4 + i;
            #pragma unroll
            for (int j = 0; j < 4; j++) {
                int kidx = s0 + tx * 4 + j;
                s[i][j] = (kidx <= t) ? s[i][j] * scale : -1e30f;
            }
        }

        #pragma unroll
        for (int i = 0; i < 4; i++) {
            float mb = fmaxf(fmaxf(s[i][0], s[i][1]), fmaxf(s[i][2], s[i][3]));
            #pragma unroll
            for (int off = 8; off; off >>= 1)
                mb = fmaxf(mb, __shfl_xor_sync(0xffffffffu, mb, off));
            float mn = fmaxf(m[i], mb);
            float alpha = __expf(m[i] - mn);
            float rs = 0.f;
            #pragma unroll
            for (int j = 0; j < 4; j++) { s[i][j] = __expf(s[i][j] - mn); rs += s[i][j]; }
            #pragma unroll
            for (int off = 8; off; off >>= 1)
                rs += __shfl_xor_sync(0xffffffffu, rs, off);
            l[i] = l[i] * alpha + rs;
            m[i] = mn;
            #pragma unroll
            for (int j = 0; j < 4; j++) o[i][j] *= alpha;
        }

        #pragma unroll
        for (int i = 0; i < 4; i++)
            #pragma unroll
            for (int j = 0; j < 4; j++)
                Ps[ty * 4 + i][tx * 4 + j] = s[i][j];
        __syncthreads();

        #pragma unroll
        for (int k4 = 0; k4 < 16; k4++) {
            float4 pr[4], vr[4];
            #pragma unroll
            for (int i = 0; i < 4; i++) pr[i] = *(const float4*)&Ps[ty * 4 + i][k4 * 4];
            #pragma unroll
            for (int kc = 0; kc < 4; kc++) vr[kc] = *(const float4*)&Vs[k4 * 4 + kc][tx * 4];
            #pragma unroll
            for (int i = 0; i < 4; i++) {
                o[i][0] += pr[i].x * vr[0].x + pr[i].y * vr[1].x + pr[i].z * vr[2].x + pr[i].w * vr[3].x;
                o[i][1] += pr[i].x * vr[0].y + pr[i].y * vr[1].y + pr[i].z * vr[2].y + pr[i].w * vr[3].y;
                o[i][2] += pr[i].x * vr[0].z + pr[i].y * vr[1].z + pr[i].z * vr[2].z + pr[i].w * vr[3].z;
                o[i][3] += pr[i].x * vr[0].w + pr[i].y * vr[1].w + pr[i].z * vr[2].w + pr[i].w * vr[3].w;
            }
        }
    }

    // write hi/lo bf16 into [B,T,H*D]
    const size_t rb = ((size_t)(b * TT + t0)) * EE + h * DD;
    #pragma unroll
    for (int i = 0; i < 4; i++) {
        float inv = 1.0f / l[i];
        size_t ro = rb + (size_t)(ty * 4 + i) * EE + tx * 4;
        #pragma unroll
        for (int j = 0; j < 4; j += 2) {
            float y0 = o[i][j] * inv, y1 = o[i][j + 1] * inv;
            __nv_bfloat16 h0 = __float2bfloat16(y0), h1 = __float2bfloat16(y1);
            __nv_bfloat162 hh; hh.x = h0; hh.y = h1;
            __nv_bfloat162 ll;
            ll.x = __float2bfloat16(y0 - __bfloat162float(h0));
            ll.y = __float2bfloat16(y1 - __bfloat162float(h1));
            *(__nv_bfloat162*)&g_ohi[ro + j] = hh;
            *(__nv_bfloat162*)&g_olo[ro + j] = ll;
        }
    }
}

// ---------------- mma.sync split-bf16 GEMM ----------------------------------
// C[M,N] = (Ahi+Alo)[M,K] @ (Bhi+Blo)[N,K]^T  (+bias) (relu) (+res)
// Block 128x128, BK=32, 8 warps (2x4), warp tile 64x32.
// 3 passes per k-step: hi*hi + hi*lo + lo*hi (lo*lo ~2^-18, dropped).
#define BKP 40   // padded row: 32 + 8 halfwords (80 B, ldmatrix conflict-free)
template <int KK, bool RELU, bool HAS_RES, bool OUTPAIR>
__global__ __launch_bounds__(256) void tc_gemm(
    const __nv_bfloat16* __restrict__ Ahi, const __nv_bfloat16* __restrict__ Alo,
    const __nv_bfloat16* __restrict__ Bhi, const __nv_bfloat16* __restrict__ Blo,
    const float* __restrict__ bias, const float* __restrict__ res,
    float* __restrict__ Cf, __nv_bfloat16* __restrict__ Chi, __nv_bfloat16* __restrict__ Clo,
    int Nc)
{
    __shared__ __nv_bfloat16 sAh[128][BKP], sAl[128][BKP];
    __shared__ __nv_bfloat16 sBh[128][BKP], sBl[128][BKP];

    const int tid = threadIdx.x;
    const int wid = tid >> 5, lane = tid & 31;
    const int wm = wid >> 2, wn = wid & 3;            // 2 x 4 warp grid
    const int m0 = blockIdx.y * 128, n0 = blockIdx.x * 128;

    const __nv_bfloat16* Amh = Ahi + (size_t)m0 * KK;
    const __nv_bfloat16* Aml = Alo + (size_t)m0 * KK;
    const __nv_bfloat16* Bmh = Bhi + (size_t)n0 * KK;
    const __nv_bfloat16* Bml = Blo + (size_t)n0 * KK;

    // ldmatrix source addresses (fixed per thread, k-step offset added later)
    const int arow = wm * 64 + (lane & 15);
    const int acol = (lane >> 4) * 8;
    const uint32_t aAh = smem_u32(&sAh[arow][acol]);
    const uint32_t aAl = smem_u32(&sAl[arow][acol]);
    const int brow = wn * 32 + (lane & 7);
    const int bcol = ((lane >> 3) & 1) * 8;
    const uint32_t aBh = smem_u32(&sBh[brow][bcol]);
    const uint32_t aBl = smem_u32(&sBl[brow][bcol]);

    float c[4][4][4];
    #pragma unroll
    for (int i = 0; i < 4; i++)
        #pragma unroll
        for (int j = 0; j < 4; j++)
            #pragma unroll
            for (int e = 0; e < 4; e++) c[i][j][e] = 0.f;

    for (int k0 = 0; k0 < KK; k0 += 32) {
        __syncthreads();   // previous compute done before overwrite
        // load 4 tiles of 128x32 bf16: 512 uint4 each; 256 thr x 2
        #pragma unroll
        for (int u = 0; u < 2; ++u) {
            int unit = tid + u * 256;          // 0..511
            int row = unit >> 2, cq = unit & 3;
            size_t go = (size_t)row * KK + k0 + cq * 8;
            *(uint4*)&sAh[row][cq * 8] = *(const uint4*)(Amh + go);
            *(uint4*)&sAl[row][cq * 8] = *(const uint4*)(Aml + go);
            *(uint4*)&sBh[row][cq * 8] = *(const uint4*)(Bmh + go);
            *(uint4*)&sBl[row][cq * 8] = *(const uint4*)(Bml + go);
        }
        __syncthreads();

        #pragma unroll
        for (int ks = 0; ks < 2; ++ks) {
            const uint32_t koff = ks * 16 * 2;          // halfwords -> bytes
            uint32_t ah[4][4], al[4][4], bh[4][2], bl[4][2];
            #pragma unroll
            for (int i = 0; i < 4; i++) {
                ldm_x4(ah[i], aAh + (uint32_t)(i * 16 * BKP * 2) + koff);
                ldm_x4(al[i], aAl + (uint32_t)(i * 16 * BKP * 2) + koff);
            }
            #pragma unroll
            for (int j = 0; j < 4; j++) {
                ldm_x2(bh[j], aBh + (uint32_t)(j * 8 * BKP * 2) + koff);
                ldm_x2(bl[j], aBl + (uint32_t)(j * 8 * BKP * 2) + koff);
            }
            #pragma unroll
            for (int i = 0; i < 4; i++)
                #pragma unroll
                for (int j = 0; j < 4; j++) {
                    mma16816(c[i][j], ah[i], bh[j]);
                    mma16816(c[i][j], ah[i], bl[j]);
                    mma16816(c[i][j], al[i], bh[j]);
                }
        }
    }

    // epilogue: atom (i,j): rows m0+wm*64+i*16 + lane/4 (+8), cols n0+wn*32+j*8+2*(lane&3)(+1)
    const int er = m0 + wm * 64 + (lane >> 2);
    const int ec = n0 + wn * 32 + (lane & 3) * 2;
    #pragma unroll
    for (int i = 0; i < 4; i++) {
        #pragma unroll
        for (int rr = 0; rr < 2; rr++) {
            const int r = er + i * 16 + rr * 8;
            #pragma unroll
            for (int j = 0; j < 4; j++) {
                const int cc = ec + j * 8;
                float v0 = c[i][j][rr * 2 + 0] + bias[cc];
                float v1 = c[i][j][rr * 2 + 1] + bias[cc + 1];
                if (RELU) { v0 = fmaxf(v0, 0.f); v1 = fmaxf(v1, 0.f); }
                if (HAS_RES) {
                    const float* rp = &res[(size_t)r * Nc + cc];
                    v0 += rp[0]; v1 += rp[1];
                }
                if (OUTPAIR) {
                    __nv_bfloat16 h0 = __float2bfloat16(v0), h1 = __float2bfloat16(v1);
                    __nv_bfloat162 hh; hh.x = h0; hh.y = h1;
                    __nv_bfloat162 ll;
                    ll.x = __float2bfloat16(v0 - __bfloat162float(h0));
                    ll.y = __float2bfloat16(v1 - __bfloat162float(h1));
                    *(__nv_bfloat162*)&Chi[(size_t)r * Nc + cc] = hh;
                    *(__nv_bfloat162*)&Clo[(size_t)r * Nc + cc] = ll;
                } else {
                    float2 ov = {v0, v1};
                    *(float2*)&Cf[(size_t)r * Nc + cc] = ov;
                }
            }
        }
    }
}

// ---------------- launch ----------------------------------------------------
extern "C" void kernel_launch(void* const* d_in, const int* in_sizes, int n_in,
                              void* d_out, int out_size) {
    const float* x   = (const float*)d_in[0];
    const float* Wq  = (const float*)d_in[1];
    const float* Wk  = (const float*)d_in[2];
    const float* Wv  = (const float*)d_in[3];
    const float* Wo  = (const float*)d_in[4];
    const float* bo  = (const float*)d_in[5];
    const float* W1  = (const float*)d_in[6];
    const float* b1  = (const float*)d_in[7];
    const float* W2  = (const float*)d_in[8];
    const float* b2  = (const float*)d_in[9];
    const float* g1  = (const float*)d_in[10];
    const float* be1 = (const float*)d_in[11];
    const float* g2  = (const float*)d_in[12];
    const float* be2 = (const float*)d_in[13];
    float* out = (float*)d_out;
    (void)in_sizes; (void)n_in; (void)out_size;

    float *xn, *x2, *xn2;
    __nv_bfloat16 *ohi, *olo, *x2hi, *x2lo, *h1hi, *h1lo;
    __nv_bfloat16 *wothi, *wotlo, *w1thi, *w1tlo, *w2thi, *w2tlo;
    cudaGetSymbolAddress((void**)&xn,   g_xn);
    cudaGetSymbolAddress((void**)&x2,   g_x2);
    cudaGetSymbolAddress((void**)&xn2,  g_xn2);
    cudaGetSymbolAddress((void**)&ohi,  g_ohi);
    cudaGetSymbolAddress((void**)&olo,  g_olo);
    cudaGetSymbolAddress((void**)&x2hi, g_x2hi);
    cudaGetSymbolAddress((void**)&x2lo, g_x2lo);
    cudaGetSymbolAddress((void**)&h1hi, g_h1hi);
    cudaGetSymbolAddress((void**)&h1lo, g_h1lo);
    cudaGetSymbolAddress((void**)&wothi, g_wothi);
    cudaGetSymbolAddress((void**)&wotlo, g_wotlo);
    cudaGetSymbolAddress((void**)&w1thi, g_w1thi);
    cudaGetSymbolAddress((void**)&w1tlo, g_w1tlo);
    cudaGetSymbolAddress((void**)&w2thi, g_w2thi);
    cudaGetSymbolAddress((void**)&w2tlo, g_w2tlo);

    const int attn_smem = 4 * 64 * 68 * (int)sizeof(float);   // 69632 B
    cudaFuncSetAttribute(attn_kernel,
                         cudaFuncAttributeMaxDynamicSharedMemorySize, attn_smem);

    // 0. weights: transpose + hi/lo split
    wsplit_kernel<<<dim3(EE / 32, EE / 32), 256>>>(Wo, wothi, wotlo, EE, EE);
    wsplit_kernel<<<dim3(HIDD / 32, EE / 32), 256>>>(W1, w1thi, w1tlo, EE, HIDD);
    wsplit_kernel<<<dim3(EE / 32, HIDD / 32), 256>>>(W2, w2thi, w2tlo, HIDD, EE);
    // 1. xn = LN1(x)
    ln_kernel<false><<<NROWS, 256>>>(x, g1, be1, xn, nullptr, nullptr);
    // 2. q,k,v
    qkv_kernel<<<dim3(TT / 64, BB * HH), 256>>>(Wq, Wk, Wv);
    // 3. causal attention -> o hi/lo [B,T,H*D]
    attn_kernel<<<dim3(TT / 64, BB * HH), 256, attn_smem>>>();
    // 4. x2 = xn + o @ Wo + bo        (mma.sync)
    tc_gemm<512, false, true, false><<<dim3(EE / 128, NROWS / 128), 256>>>(
        ohi, olo, wothi, wotlo, bo, xn, x2, nullptr, nullptr, EE);
    // 5. xn2 = LN2(x2)  (fp32 + pair)
    ln_kernel<true><<<NROWS, 256>>>(x2, g2, be2, xn2, x2hi, x2lo);
    // 6. h1 = relu(xn2 @ W1 + b1)     (mma.sync, bf16-pair out)
    tc_gemm<512, true, false, true><<<dim3(HIDD / 128, NROWS / 128), 256>>>(
        x2hi, x2lo, w1thi, w1tlo, b1, nullptr, nullptr, h1hi, h1lo, HIDD);
    // 7. out = xn2 + h1 @ W2 + b2     (mma.sync)
    tc_gemm<4096, false, true, false><<<dim3(EE / 128, NROWS / 128), 256>>>(
        h1hi, h1lo, w2thi, w2tlo, b2, xn2, out, nullptr, nullptr, EE);
}

// round 15
// speedup vs baseline: 1.7510x; 1.0659x over previous
#include <cuda_runtime.h>
#include <cuda_bf16.h>
#include <stdint.h>
#include <math.h>

#define BB 4
#define TT 2048
#define EE 512
#define HH 8
#define DD 64
#define HIDD 4096
#define NROWS (BB*TT)            // 8192

// ---------------- scratch (static device globals; no runtime allocation) ----
__device__ float g_xn [NROWS*EE];        // LN1 output (fp32 residual for step 4)
__device__ float g_q  [NROWS*EE];        // [B,T,H*D] fp32
__device__ float g_k  [NROWS*EE];
__device__ float g_v  [NROWS*EE];
__device__ float g_x2 [NROWS*EE];        // xn + mha
__device__ float g_xn2[NROWS*EE];        // LN2 output fp32 (residual for step 7)

// bf16 hi/lo split pairs (fp32 ~= hi + lo)
__device__ __align__(16) __nv_bfloat16 g_xnhi[NROWS*EE],  g_xnlo[NROWS*EE];   // LN1 pair
__device__ __align__(16) __nv_bfloat16 g_ohi [NROWS*EE],  g_olo [NROWS*EE];   // attn out
__device__ __align__(16) __nv_bfloat16 g_x2hi[NROWS*EE],  g_x2lo[NROWS*EE];   // xn2 pair
__device__ __align__(16) __nv_bfloat16 g_h1hi[NROWS*HIDD], g_h1lo[NROWS*HIDD]; // FFN hidden
__device__ __align__(16) __nv_bfloat16 g_wothi[EE*EE],   g_wotlo[EE*EE];      // Wo^T
__device__ __align__(16) __nv_bfloat16 g_w1thi[HIDD*EE], g_w1tlo[HIDD*EE];    // W1^T
__device__ __align__(16) __nv_bfloat16 g_w2thi[EE*HIDD], g_w2tlo[EE*HIDD];    // W2^T
__device__ __align__(16) __nv_bfloat16 g_wqthi[EE*EE],   g_wqtlo[EE*EE];      // Wq^T [H*D, E]
__device__ __align__(16) __nv_bfloat16 g_wkthi[EE*EE],   g_wktlo[EE*EE];
__device__ __align__(16) __nv_bfloat16 g_wvthi[EE*EE],   g_wvtlo[EE*EE];

// ---------------- helpers ----------------------------------------------------
static __device__ __forceinline__ uint32_t smem_u32(const void* p) {
    uint32_t a;
    asm("{ .reg .u64 t; cvta.to.shared.u64 t, %1; cvt.u32.u64 %0, t; }" : "=r"(a) : "l"(p));
    return a;
}
static __device__ __forceinline__ void ldm_x4(uint32_t* r, uint32_t addr) {
    asm volatile("ldmatrix.sync.aligned.m8n8.x4.shared.b16 {%0,%1,%2,%3}, [%4];"
                 : "=r"(r[0]), "=r"(r[1]), "=r"(r[2]), "=r"(r[3]) : "r"(addr));
}
static __device__ __forceinline__ void ldm_x2(uint32_t* r, uint32_t addr) {
    asm volatile("ldmatrix.sync.aligned.m8n8.x2.shared.b16 {%0,%1}, [%2];"
                 : "=r"(r[0]), "=r"(r[1]) : "r"(addr));
}
static __device__ __forceinline__ void mma16816(float* c, const uint32_t* a, const uint32_t* b) {
    asm volatile("mma.sync.aligned.m16n8k16.row.col.f32.bf16.bf16.f32 "
                 "{%0,%1,%2,%3}, {%4,%5,%6,%7}, {%8,%9}, {%0,%1,%2,%3};"
                 : "+f"(c[0]), "+f"(c[1]), "+f"(c[2]), "+f"(c[3])
                 : "r"(a[0]), "r"(a[1]), "r"(a[2]), "r"(a[3]), "r"(b[0]), "r"(b[1]));
}
static __device__ __forceinline__ void cp16(uint32_t s, const void* g) {
    asm volatile("cp.async.cg.shared.global [%0], [%1], 16;" :: "r"(s), "l"(g));
}
// fast exp on FMA pipe (attention is MUFU-bound otherwise): rel err ~1.5e-6
static __device__ __forceinline__ float fexp(float x) {
    float y = fmaxf(x * 1.4426950408889634f, -126.0f);
    float t = y + 12582912.0f;                 // 1.5*2^23: round-to-nearest int
    int   n = __float_as_int(t) - 0x4B400000;
    float f = y - (t - 12582912.0f);           // f in [-0.5, 0.5]
    float p = 1.3333558146e-3f;
    p = fmaf(p, f, 9.6181291076e-3f);
    p = fmaf(p, f, 5.5504108664e-2f);
    p = fmaf(p, f, 2.4022650696e-1f);
    p = fmaf(p, f, 6.9314718056e-1f);
    p = fmaf(p, f, 1.0f);
    return __int_as_float(__float_as_int(p) + (n << 23));   // p in [0.707,1.415]
}

// ---------------- LayerNorm (emits fp32 + bf16 hi/lo pair) -------------------
__global__ __launch_bounds__(256) void ln_kernel(const float* __restrict__ x,
                                                 const float* __restrict__ g,
                                                 const float* __restrict__ b,
                                                 float* __restrict__ out,
                                                 __nv_bfloat16* __restrict__ ohi,
                                                 __nv_bfloat16* __restrict__ olo) {
    const int row = blockIdx.x;
    const int tid = threadIdx.x;
    const float* xr = x + (size_t)row * EE;
    float v0 = xr[tid];
    float v1 = xr[tid + 256];
    float s  = v0 + v1;
    float ss = v0 * v0 + v1 * v1;
    #pragma unroll
    for (int off = 16; off; off >>= 1) {
        s  += __shfl_xor_sync(0xffffffffu, s,  off);
        ss += __shfl_xor_sync(0xffffffffu, ss, off);
    }
    __shared__ float sh_s[8], sh_ss[8];
    const int w = tid >> 5, ln = tid & 31;
    if (ln == 0) { sh_s[w] = s; sh_ss[w] = ss; }
    __syncthreads();
    float ts = 0.f, tss = 0.f;
    #pragma unroll
    for (int i = 0; i < 8; i++) { ts += sh_s[i]; tss += sh_ss[i]; }
    const float mean = ts * (1.0f / EE);
    const float var  = tss * (1.0f / EE) - mean * mean;
    const float inv  = rsqrtf(var + 1e-5f);
    float y0 = (v0 - mean) * inv * g[tid]       + b[tid];
    float y1 = (v1 - mean) * inv * g[tid + 256] + b[tid + 256];
    out[(size_t)row * EE + tid]       = y0;
    out[(size_t)row * EE + tid + 256] = y1;
    __nv_bfloat16 h0 = __float2bfloat16(y0);
    __nv_bfloat16 h1 = __float2bfloat16(y1);
    ohi[(size_t)row * EE + tid]       = h0;
    ohi[(size_t)row * EE + tid + 256] = h1;
    olo[(size_t)row * EE + tid]       = __float2bfloat16(y0 - __bfloat162float(h0));
    olo[(size_t)row * EE + tid + 256] = __float2bfloat16(y1 - __bfloat162float(h1));
}

// ---------------- weight transpose + hi/lo split ----------------------------
// W [K, N] fp32 row-major -> T_hi/T_lo [N, K] bf16.
__global__ __launch_bounds__(256) void wsplit_kernel(const float* __restrict__ W,
                                                     __nv_bfloat16* __restrict__ Thi,
                                                     __nv_bfloat16* __restrict__ Tlo,
                                                     int K, int N) {
    __shared__ float t[32][33];
    const int n0 = blockIdx.x * 32, k0 = blockIdx.y * 32;
    const int tx = threadIdx.x & 31, ty = threadIdx.x >> 5;
    #pragma unroll
    for (int i = ty; i < 32; i += 8)
        t[i][tx] = W[(size_t)(k0 + i) * N + n0 + tx];
    __syncthreads();
    #pragma unroll
    for (int i = ty; i < 32; i += 8) {
        float v = t[tx][i];
        __nv_bfloat16 h = __float2bfloat16(v);
        Thi[(size_t)(n0 + i) * K + k0 + tx] = h;
        Tlo[(size_t)(n0 + i) * K + k0 + tx] = __float2bfloat16(v - __bfloat162float(h));
    }
}

// W [H][E][D] -> T [H*D][E] (per-head transpose + split)
__global__ __launch_bounds__(256) void wsplit_qkv(const float* __restrict__ W,
                                                  __nv_bfloat16* __restrict__ Thi,
                                                  __nv_bfloat16* __restrict__ Tlo) {
    __shared__ float t[32][33];
    const int h = blockIdx.z;
    const int d0 = blockIdx.x * 32, e0 = blockIdx.y * 32;
    const int tx = threadIdx.x & 31, ty = threadIdx.x >> 5;
    const float* Wh = W + (size_t)h * EE * DD;
    #pragma unroll
    for (int i = ty; i < 32; i += 8)
        t[i][tx] = Wh[(size_t)(e0 + i) * DD + d0 + tx];
    __syncthreads();
    #pragma unroll
    for (int i = ty; i < 32; i += 8) {
        float v = t[tx][i];                  // W[h][e0+tx][d0+i]
        __nv_bfloat16 hh = __float2bfloat16(v);
        Thi[(size_t)(h * DD + d0 + i) * EE + e0 + tx] = hh;
        Tlo[(size_t)(h * DD + d0 + i) * EE + e0 + tx] =
            __float2bfloat16(v - __bfloat162float(hh));
    }
}

// ---------------- flash attention (q/k/v in [B,T,H*D] fp32) ------------------
__global__ __launch_bounds__(256) void attn_kernel() {
    extern __shared__ float sm[];
    float (*Qs)[68] = reinterpret_cast<float (*)[68]>(sm);
    float (*Ks)[68] = reinterpret_cast<float (*)[68]>(sm + 64 * 68);
    float (*Vs)[68] = reinterpret_cast<float (*)[68]>(sm + 2 * 64 * 68);
    float (*Ps)[68] = reinterpret_cast<float (*)[68]>(sm + 3 * 64 * 68);

    const int t0 = blockIdx.x * 64;
    const int bh = blockIdx.y;
    const int b = bh >> 3, h = bh & 7;
    const int tid = threadIdx.x;
    const int tx = tid & 15, ty = tid >> 4;

    const float* qp = g_q + ((size_t)(b * TT + t0)) * EE + h * DD;
    const float* kp = g_k + (size_t)b * TT * EE + h * DD;
    const float* vp = g_v + (size_t)b * TT * EE + h * DD;

    #pragma unroll
    for (int it = 0; it < 4; it++) {
        int idx = tid + it * 256;
        int r = idx >> 4, c4 = idx & 15;
        *(float4*)&Qs[r][c4 * 4] = *(const float4*)&qp[(size_t)r * EE + c4 * 4];
    }

    float m[4], l[4], o[4][4];
    #pragma unroll
    for (int i = 0; i < 4; i++) {
        m[i] = -1e30f; l[i] = 0.f;
        #pragma unroll
        for (int j = 0; j < 4; j++) o[i][j] = 0.f;
    }

    const float scale = 0.022097086912079608f;   // 2048^-0.5

    for (int s0 = 0; s0 <= t0; s0 += 64) {
        __syncthreads();
        #pragma unroll
        for (int it = 0; it < 4; it++) {
            int idx = tid + it * 256;
            int r = idx >> 4, c4 = idx & 15;
            *(float4*)&Ks[r][c4 * 4] = *(const float4*)&kp[(size_t)(s0 + r) * EE + c4 * 4];
            *(float4*)&Vs[r][c4 * 4] = *(const float4*)&vp[(size_t)(s0 + r) * EE + c4 * 4];
        }
        __syncthreads();

        float s[4][4] = {};
        #pragma unroll
        for (int d4 = 0; d4 < 16; d4++) {
            float4 aa[4], bb[4];
            #pragma unroll
            for (int i = 0; i < 4; i++) aa[i] = *(const float4*)&Qs[ty * 4 + i][d4 * 4];
            #pragma unroll
            for (int j = 0; j < 4; j++) bb[j] = *(const float4*)&Ks[tx * 4 + j][d4 * 4];
            #pragma unroll
            for (int i = 0; i < 4; i++)
                #pragma unroll
                for (int j = 0; j < 4; j++)
                    s[i][j] += aa[i].x * bb[j].x + aa[i].y * bb[j].y +
                               aa[i].z * bb[j].z + aa[i].w * bb[j].w;
        }

        #pragma unroll
        for (int i = 0; i < 4; i++) {
            int t = t0 + ty * 4 + i;
            #pragma unroll
            for (int j = 0; j < 4; j++) {
                int kidx = s0 + tx * 4 + j;
                s[i][j] = (kidx <= t) ? s[i][j] * scale : -1e30f;
            }
        }

        #pragma unroll
        for (int i = 0; i < 4; i++) {
            float mb = fmaxf(fmaxf(s[i][0], s[i][1]), fmaxf(s[i][2], s[i][3]));
            #pragma unroll
            for (int off = 8; off; off >>= 1)
                mb = fmaxf(mb, __shfl_xor_sync(0xffffffffu, mb, off));
            float mn = fmaxf(m[i], mb);
            float alpha = fexp(m[i] - mn);
            float rs = 0.f;
            #pragma unroll
            for (int j = 0; j < 4; j++) { s[i][j] = fexp(s[i][j] - mn); rs += s[i][j]; }
            #pragma unroll
            for (int off = 8; off; off >>= 1)
                rs += __shfl_xor_sync(0xffffffffu, rs, off);
            l[i] = l[i] * alpha + rs;
            m[i] = mn;
            #pragma unroll
            for (int j = 0; j < 4; j++) o[i][j] *= alpha;
        }

        #pragma unroll
        for (int i = 0; i < 4; i++)
            #pragma unroll
            for (int j = 0; j < 4; j++)
                Ps[ty * 4 + i][tx * 4 + j] = s[i][j];
        __syncthreads();

        #pragma unroll
        for (int k4 = 0; k4 < 16; k4++) {
            float4 pr[4], vr[4];
            #pragma unroll
            for (int i = 0; i < 4; i++) pr[i] = *(const float4*)&Ps[ty * 4 + i][k4 * 4];
            #pragma unroll
            for (int kc = 0; kc < 4; kc++) vr[kc] = *(const float4*)&Vs[k4 * 4 + kc][tx * 4];
            #pragma unroll
            for (int i = 0; i < 4; i++) {
                o[i][0] += pr[i].x * vr[0].x + pr[i].y * vr[1].x + pr[i].z * vr[2].x + pr[i].w * vr[3].x;
                o[i][1] += pr[i].x * vr[0].y + pr[i].y * vr[1].y + pr[i].z * vr[2].y + pr[i].w * vr[3].y;
                o[i][2] += pr[i].x * vr[0].z + pr[i].y * vr[1].z + pr[i].z * vr[2].z + pr[i].w * vr[3].z;
                o[i][3] += pr[i].x * vr[0].w + pr[i].y * vr[1].w + pr[i].z * vr[2].w + pr[i].w * vr[3].w;
            }
        }
    }

    const size_t rb = ((size_t)(b * TT + t0)) * EE + h * DD;
    #pragma unroll
    for (int i = 0; i < 4; i++) {
        float inv = 1.0f / l[i];
        size_t ro = rb + (size_t)(ty * 4 + i) * EE + tx * 4;
        #pragma unroll
        for (int j = 0; j < 4; j += 2) {
            float y0 = o[i][j] * inv, y1 = o[i][j + 1] * inv;
            __nv_bfloat16 h0 = __float2bfloat16(y0), h1 = __float2bfloat16(y1);
            __nv_bfloat162 hh; hh.x = h0; hh.y = h1;
            __nv_bfloat162 ll;
            ll.x = __float2bfloat16(y0 - __bfloat162float(h0));
            ll.y = __float2bfloat16(y1 - __bfloat162float(h1));
            *(__nv_bfloat162*)&g_ohi[ro + j] = hh;
            *(__nv_bfloat162*)&g_olo[ro + j] = ll;
        }
    }
}

// ---------------- mma.sync split-bf16 GEMM, cp.async 2-stage -----------------
// C[M,N] = (Ahi+Alo)[M,K] @ (Bhi+Blo)[N,K]^T  (+bias) (relu) (+res)
#define BKP 40                        // padded row: 32 + 8 halfwords
#define TILEB (128 * BKP * 2)         // 10240 B per tile
#define STAGEB (4 * TILEB)            // 40960 B per stage (Ah, Al, Bh, Bl)
template <int KK, bool HAS_BIAS, bool RELU, bool HAS_RES, bool OUTPAIR>
__global__ __launch_bounds__(256) void tc_gemm(
    const __nv_bfloat16* __restrict__ Ahi, const __nv_bfloat16* __restrict__ Alo,
    const __nv_bfloat16* __restrict__ Bhi, const __nv_bfloat16* __restrict__ Blo,
    const float* __restrict__ bias, const float* __restrict__ res,
    float* __restrict__ Cf, __nv_bfloat16* __restrict__ Chi, __nv_bfloat16* __restrict__ Clo,
    int Nc)
{
    extern __shared__ char smem[];
    const uint32_t sb = smem_u32(smem);
    const int tid = threadIdx.x;
    const int wid = tid >> 5, lane = tid & 31;
    const int wm = wid >> 2, wn = wid & 3;            // 2 x 4 warp grid
    const int m0 = blockIdx.y * 128, n0 = blockIdx.x * 128;

    const __nv_bfloat16* Amh = Ahi + (size_t)m0 * KK;
    const __nv_bfloat16* Aml = Alo + (size_t)m0 * KK;
    const __nv_bfloat16* Bmh = Bhi + (size_t)n0 * KK;
    const __nv_bfloat16* Bml = Blo + (size_t)n0 * KK;

    // per-thread copy coords (2 rows of uint4 per tile)
    const int prow0 = tid >> 2, pcq = tid & 3;
    const uint32_t poff0 = (uint32_t)(prow0 * BKP + pcq * 8) * 2;
    const uint32_t poff1 = (uint32_t)((prow0 + 64) * BKP + pcq * 8) * 2;

    // ldmatrix addresses (offsets within a stage)
    const int arow = wm * 64 + (lane & 15), acol = (lane >> 4) * 8;
    const uint32_t oA = (uint32_t)(arow * BKP + acol) * 2;
    const int brow = wn * 32 + (lane & 7), bcol = ((lane >> 3) & 1) * 8;
    const uint32_t oB = (uint32_t)(brow * BKP + bcol) * 2;

    float c[4][4][4];
    #pragma unroll
    for (int i = 0; i < 4; i++)
        #pragma unroll
        for (int j = 0; j < 4; j++)
            #pragma unroll
            for (int e = 0; e < 4; e++) c[i][j][e] = 0.f;

    auto pf = [&](int kt, int st) {
        const int k0 = kt * 32;
        const uint32_t sbase = sb + (uint32_t)st * STAGEB;
        size_t g0 = (size_t)prow0 * KK + k0 + pcq * 8;
        size_t g1 = (size_t)(prow0 + 64) * KK + k0 + pcq * 8;
        cp16(sbase + poff0,             Amh + g0);
        cp16(sbase + poff1,             Amh + g1);
        cp16(sbase + TILEB + poff0,     Aml + g0);
        cp16(sbase + TILEB + poff1,     Aml + g1);
        cp16(sbase + 2 * TILEB + poff0, Bmh + g0);
        cp16(sbase + 2 * TILEB + poff1, Bmh + g1);
        cp16(sbase + 3 * TILEB + poff0, Bml + g0);
        cp16(sbase + 3 * TILEB + poff1, Bml + g1);
    };

    constexpr int NT = KK / 32;
    pf(0, 0);
    asm volatile("cp.async.commit_group;");
    for (int kt = 0; kt < NT; ++kt) {
        const int st = kt & 1;
        if (kt + 1 < NT) {
            pf(kt + 1, st ^ 1);
            asm volatile("cp.async.commit_group;");
            asm volatile("cp.async.wait_group 1;");
        } else {
            asm volatile("cp.async.wait_group 0;");
        }
        __syncthreads();
        const uint32_t sbase = sb + (uint32_t)st * STAGEB;
        #pragma unroll
        for (int ks = 0; ks < 2; ++ks) {
            const uint32_t koff = ks * 32;          // 16 halfwords
            uint32_t ah[4][4], al[4][4], bh[4][2], bl[4][2];
            #pragma unroll
            for (int i = 0; i < 4; i++) {
                ldm_x4(ah[i], sbase + oA + (uint32_t)(i * 16 * BKP * 2) + koff);
                ldm_x4(al[i], sbase + TILEB + oA + (uint32_t)(i * 16 * BKP * 2) + koff);
            }
            #pragma unroll
            for (int j = 0; j < 4; j++) {
                ldm_x2(bh[j], sbase + 2 * TILEB + oB + (uint32_t)(j * 8 * BKP * 2) + koff);
                ldm_x2(bl[j], sbase + 3 * TILEB + oB + (uint32_t)(j * 8 * BKP * 2) + koff);
            }
            #pragma unroll
            for (int i = 0; i < 4; i++)
                #pragma unroll
                for (int j = 0; j < 4; j++) {
                    mma16816(c[i][j], ah[i], bh[j]);
                    mma16816(c[i][j], ah[i], bl[j]);
                    mma16816(c[i][j], al[i], bh[j]);
                }
        }
        __syncthreads();
    }

    const int er = m0 + wm * 64 + (lane >> 2);
    const int ec = n0 + wn * 32 + (lane & 3) * 2;
    #pragma unroll
    for (int i = 0; i < 4; i++) {
        #pragma unroll
        for (int rr = 0; rr < 2; rr++) {
            const int r = er + i * 16 + rr * 8;
            #pragma unroll
            for (int j = 0; j < 4; j++) {
                const int cc = ec + j * 8;
                float v0 = c[i][j][rr * 2 + 0];
                float v1 = c[i][j][rr * 2 + 1];
                if (HAS_BIAS) { v0 += bias[cc]; v1 += bias[cc + 1]; }
                if (RELU) { v0 = fmaxf(v0, 0.f); v1 = fmaxf(v1, 0.f); }
                if (HAS_RES) {
                    const float* rp = &res[(size_t)r * Nc + cc];
                    v0 += rp[0]; v1 += rp[1];
                }
                if (OUTPAIR) {
                    __nv_bfloat16 h0 = __float2bfloat16(v0), h1 = __float2bfloat16(v1);
                    __nv_bfloat162 hh; hh.x = h0; hh.y = h1;
                    __nv_bfloat162 ll;
                    ll.x = __float2bfloat16(v0 - __bfloat162float(h0));
                    ll.y = __float2bfloat16(v1 - __bfloat162float(h1));
                    *(__nv_bfloat162*)&Chi[(size_t)r * Nc + cc] = hh;
                    *(__nv_bfloat162*)&Clo[(size_t)r * Nc + cc] = ll;
                } else {
                    float2 ov = {v0, v1};
                    *(float2*)&Cf[(size_t)r * Nc + cc] = ov;
                }
            }
        }
    }
}

// ---------------- launch ----------------------------------------------------
extern "C" void kernel_launch(void* const* d_in, const int* in_sizes, int n_in,
                              void* d_out, int out_size) {
    const float* x   = (const float*)d_in[0];
    const float* Wq  = (const float*)d_in[1];
    const float* Wk  = (const float*)d_in[2];
    const float* Wv  = (const float*)d_in[3];
    const float* Wo  = (const float*)d_in[4];
    const float* bo  = (const float*)d_in[5];
    const float* W1  = (const float*)d_in[6];
    const float* b1  = (const float*)d_in[7];
    const float* W2  = (const float*)d_in[8];
    const float* b2  = (const float*)d_in[9];
    const float* g1  = (const float*)d_in[10];
    const float* be1 = (const float*)d_in[11];
    const float* g2  = (const float*)d_in[12];
    const float* be2 = (const float*)d_in[13];
    float* out = (float*)d_out;
    (void)in_sizes; (void)n_in; (void)out_size;

    float *xn, *x2, *xn2, *q, *k, *v;
    __nv_bfloat16 *xnhi, *xnlo, *ohi, *olo, *x2hi, *x2lo, *h1hi, *h1lo;
    __nv_bfloat16 *wothi, *wotlo, *w1thi, *w1tlo, *w2thi, *w2tlo;
    __nv_bfloat16 *wqthi, *wqtlo, *wkthi, *wktlo, *wvthi, *wvtlo;
    cudaGetSymbolAddress((void**)&xn,   g_xn);
    cudaGetSymbolAddress((void**)&x2,   g_x2);
    cudaGetSymbolAddress((void**)&xn2,  g_xn2);
    cudaGetSymbolAddress((void**)&q,    g_q);
    cudaGetSymbolAddress((void**)&k,    g_k);
    cudaGetSymbolAddress((void**)&v,    g_v);
    cudaGetSymbolAddress((void**)&xnhi, g_xnhi);
    cudaGetSymbolAddress((void**)&xnlo, g_xnlo);
    cudaGetSymbolAddress((void**)&ohi,  g_ohi);
    cudaGetSymbolAddress((void**)&olo,  g_olo);
    cudaGetSymbolAddress((void**)&x2hi, g_x2hi);
    cudaGetSymbolAddress((void**)&x2lo, g_x2lo);
    cudaGetSymbolAddress((void**)&h1hi, g_h1hi);
    cudaGetSymbolAddress((void**)&h1lo, g_h1lo);
    cudaGetSymbolAddress((void**)&wothi, g_wothi);
    cudaGetSymbolAddress((void**)&wotlo, g_wotlo);
    cudaGetSymbolAddress((void**)&w1thi, g_w1thi);
    cudaGetSymbolAddress((void**)&w1tlo, g_w1tlo);
    cudaGetSymbolAddress((void**)&w2thi, g_w2thi);
    cudaGetSymbolAddress((void**)&w2tlo, g_w2tlo);
    cudaGetSymbolAddress((void**)&wqthi, g_wqthi);
    cudaGetSymbolAddress((void**)&wqtlo, g_wqtlo);
    cudaGetSymbolAddress((void**)&wkthi, g_wkthi);
    cudaGetSymbolAddress((void**)&wktlo, g_wktlo);
    cudaGetSymbolAddress((void**)&wvthi, g_wvthi);
    cudaGetSymbolAddress((void**)&wvtlo, g_wvtlo);

    const int attn_smem = 4 * 64 * 68 * (int)sizeof(float);   // 69632 B
    cudaFuncSetAttribute(attn_kernel,
                         cudaFuncAttributeMaxDynamicSharedMemorySize, attn_smem);
    const int tc_smem = 2 * STAGEB;                           // 81920 B
    cudaFuncSetAttribute(tc_gemm<512, false, false, false, false>,
                         cudaFuncAttributeMaxDynamicSharedMemorySize, tc_smem);
    cudaFuncSetAttribute(tc_gemm<512, true, false, true, false>,
                         cudaFuncAttributeMaxDynamicSharedMemorySize, tc_smem);
    cudaFuncSetAttribute(tc_gemm<512, true, true, false, true>,
                         cudaFuncAttributeMaxDynamicSharedMemorySize, tc_smem);
    cudaFuncSetAttribute(tc_gemm<4096, true, false, true, false>,
                         cudaFuncAttributeMaxDynamicSharedMemorySize, tc_smem);

    // 0. weight prep
    wsplit_kernel<<<dim3(EE / 32, EE / 32), 256>>>(Wo, wothi, wotlo, EE, EE);
    wsplit_kernel<<<dim3(HIDD / 32, EE / 32), 256>>>(W1, w1thi, w1tlo, EE, HIDD);
    wsplit_kernel<<<dim3(EE / 32, HIDD / 32), 256>>>(W2, w2thi, w2tlo, HIDD, EE);
    wsplit_qkv<<<dim3(DD / 32, EE / 32, HH), 256>>>(Wq, wqthi, wqtlo);
    wsplit_qkv<<<dim3(DD / 32, EE / 32, HH), 256>>>(Wk, wkthi, wktlo);
    wsplit_qkv<<<dim3(DD / 32, EE / 32, HH), 256>>>(Wv, wvthi, wvtlo);
    // 1. xn = LN1(x)  (fp32 + pair)
    ln_kernel<<<NROWS, 256>>>(x, g1, be1, xn, xnhi, xnlo);
    // 2. q,k,v = xn @ W{q,k,v}  (tensor cores, fp32 out in [B,T,H*D])
    tc_gemm<512, false, false, false, false><<<dim3(EE / 128, NROWS / 128), 256, tc_smem>>>(
        xnhi, xnlo, wqthi, wqtlo, nullptr, nullptr, q, nullptr, nullptr, EE);
    tc_gemm<512, false, false, false, false><<<dim3(EE / 128, NROWS / 128), 256, tc_smem>>>(
        xnhi, xnlo, wkthi, wktlo, nullptr, nullptr, k, nullptr, nullptr, EE);
    tc_gemm<512, false, false, false, false><<<dim3(EE / 128, NROWS / 128), 256, tc_smem>>>(
        xnhi, xnlo, wvthi, wvtlo, nullptr, nullptr, v, nullptr, nullptr, EE);
    // 3. causal attention -> o hi/lo [B,T,H*D]
    attn_kernel<<<dim3(TT / 64, BB * HH), 256, attn_smem>>>();
    // 4. x2 = xn + o @ Wo + bo
    tc_gemm<512, true, false, true, false><<<dim3(EE / 128, NROWS / 128), 256, tc_smem>>>(
        ohi, olo, wothi, wotlo, bo, xn, x2, nullptr, nullptr, EE);
    // 5. xn2 = LN2(x2)
    ln_kernel<<<NROWS, 256>>>(x2, g2, be2, xn2, x2hi, x2lo);
    // 6. h1 = relu(xn2 @ W1 + b1)
    tc_gemm<512, true, true, false, true><<<dim3(HIDD / 128, NROWS / 128), 256, tc_smem>>>(
        x2hi, x2lo, w1thi, w1tlo, b1, nullptr, nullptr, h1hi, h1lo, HIDD);
    // 7. out = xn2 + h1 @ W2 + b2
    tc_gemm<4096, true, false, true, false><<<dim3(EE / 128, NROWS / 128), 256, tc_smem>>>(
        h1hi, h1lo, w2thi, w2tlo, b2, xn2, out, nullptr, nullptr, EE);
}

// round 16
// speedup vs baseline: 2.8535x; 1.6296x over previous
#include <cuda_runtime.h>
#include <cuda_bf16.h>
#include <stdint.h>
#include <math.h>

#define BB 4
#define TT 2048
#define EE 512
#define HH 8
#define DD 64
#define HIDD 4096
#define NROWS (BB*TT)            // 8192

// ---------------- scratch (static device globals; no runtime allocation) ----
__device__ float g_xn [NROWS*EE];        // LN1 output (fp32 residual for step 4)
__device__ float g_x2 [NROWS*EE];        // xn + mha
__device__ float g_xn2[NROWS*EE];        // LN2 output fp32 (residual for step 7)

// bf16 hi/lo split pairs (fp32 ~= hi + lo)
__device__ __align__(16) __nv_bfloat16 g_xnhi[NROWS*EE],  g_xnlo[NROWS*EE];   // LN1 pair
__device__ __align__(16) __nv_bfloat16 g_qhi [NROWS*EE],  g_qlo [NROWS*EE];   // q [B,T,H*D]
__device__ __align__(16) __nv_bfloat16 g_khi [NROWS*EE],  g_klo [NROWS*EE];
__device__ __align__(16) __nv_bfloat16 g_vhi [NROWS*EE],  g_vlo [NROWS*EE];
__device__ __align__(16) __nv_bfloat16 g_ohi [NROWS*EE],  g_olo [NROWS*EE];   // attn out
__device__ __align__(16) __nv_bfloat16 g_x2hi[NROWS*EE],  g_x2lo[NROWS*EE];   // xn2 pair
__device__ __align__(16) __nv_bfloat16 g_h1hi[NROWS*HIDD], g_h1lo[NROWS*HIDD]; // FFN hidden
__device__ __align__(16) __nv_bfloat16 g_wothi[EE*EE],   g_wotlo[EE*EE];      // Wo^T
__device__ __align__(16) __nv_bfloat16 g_w1thi[HIDD*EE], g_w1tlo[HIDD*EE];    // W1^T
__device__ __align__(16) __nv_bfloat16 g_w2thi[EE*HIDD], g_w2tlo[EE*HIDD];    // W2^T
__device__ __align__(16) __nv_bfloat16 g_wqthi[EE*EE],   g_wqtlo[EE*EE];      // Wq^T [H*D, E]
__device__ __align__(16) __nv_bfloat16 g_wkthi[EE*EE],   g_wktlo[EE*EE];
__device__ __align__(16) __nv_bfloat16 g_wvthi[EE*EE],   g_wvtlo[EE*EE];

// ---------------- helpers ----------------------------------------------------
static __device__ __forceinline__ uint32_t smem_u32(const void* p) {
    uint32_t a;
    asm("{ .reg .u64 t; cvta.to.shared.u64 t, %1; cvt.u32.u64 %0, t; }" : "=r"(a) : "l"(p));
    return a;
}
static __device__ __forceinline__ void ldm_x4(uint32_t* r, uint32_t addr) {
    asm volatile("ldmatrix.sync.aligned.m8n8.x4.shared.b16 {%0,%1,%2,%3}, [%4];"
                 : "=r"(r[0]), "=r"(r[1]), "=r"(r[2]), "=r"(r[3]) : "r"(addr));
}
static __device__ __forceinline__ void ldm_x2(uint32_t* r, uint32_t addr) {
    asm volatile("ldmatrix.sync.aligned.m8n8.x2.shared.b16 {%0,%1}, [%2];"
                 : "=r"(r[0]), "=r"(r[1]) : "r"(addr));
}
static __device__ __forceinline__ void ldm_x2t(uint32_t* r, uint32_t addr) {
    asm volatile("ldmatrix.sync.aligned.m8n8.x2.trans.shared.b16 {%0,%1}, [%2];"
                 : "=r"(r[0]), "=r"(r[1]) : "r"(addr));
}
static __device__ __forceinline__ void mma16816(float* c, const uint32_t* a, const uint32_t* b) {
    asm volatile("mma.sync.aligned.m16n8k16.row.col.f32.bf16.bf16.f32 "
                 "{%0,%1,%2,%3}, {%4,%5,%6,%7}, {%8,%9}, {%0,%1,%2,%3};"
                 : "+f"(c[0]), "+f"(c[1]), "+f"(c[2]), "+f"(c[3])
                 : "r"(a[0]), "r"(a[1]), "r"(a[2]), "r"(a[3]), "r"(b[0]), "r"(b[1]));
}
static __device__ __forceinline__ void cp16(uint32_t s, const void* g) {
    asm volatile("cp.async.cg.shared.global [%0], [%1], 16;" :: "r"(s), "l"(g));
}
// fast exp on FMA pipe: rel err ~1.5e-6
static __device__ __forceinline__ float fexp(float x) {
    float y = fmaxf(x * 1.4426950408889634f, -126.0f);
    float t = y + 12582912.0f;
    int   n = __float_as_int(t) - 0x4B400000;
    float f = y - (t - 12582912.0f);
    float p = 1.3333558146e-3f;
    p = fmaf(p, f, 9.6181291076e-3f);
    p = fmaf(p, f, 5.5504108664e-2f);
    p = fmaf(p, f, 2.4022650696e-1f);
    p = fmaf(p, f, 6.9314718056e-1f);
    p = fmaf(p, f, 1.0f);
    return __int_as_float(__float_as_int(p) + (n << 23));
}

// ---------------- LayerNorm (emits fp32 + bf16 hi/lo pair) -------------------
__global__ __launch_bounds__(256) void ln_kernel(const float* __restrict__ x,
                                                 const float* __restrict__ g,
                                                 const float* __restrict__ b,
                                                 float* __restrict__ out,
                                                 __nv_bfloat16* __restrict__ ohi,
                                                 __nv_bfloat16* __restrict__ olo) {
    const int row = blockIdx.x;
    const int tid = threadIdx.x;
    const float* xr = x + (size_t)row * EE;
    float v0 = xr[tid];
    float v1 = xr[tid + 256];
    float s  = v0 + v1;
    float ss = v0 * v0 + v1 * v1;
    #pragma unroll
    for (int off = 16; off; off >>= 1) {
        s  += __shfl_xor_sync(0xffffffffu, s,  off);
        ss += __shfl_xor_sync(0xffffffffu, ss, off);
    }
    __shared__ float sh_s[8], sh_ss[8];
    const int w = tid >> 5, ln = tid & 31;
    if (ln == 0) { sh_s[w] = s; sh_ss[w] = ss; }
    __syncthreads();
    float ts = 0.f, tss = 0.f;
    #pragma unroll
    for (int i = 0; i < 8; i++) { ts += sh_s[i]; tss += sh_ss[i]; }
    const float mean = ts * (1.0f / EE);
    const float var  = tss * (1.0f / EE) - mean * mean;
    const float inv  = rsqrtf(var + 1e-5f);
    float y0 = (v0 - mean) * inv * g[tid]       + b[tid];
    float y1 = (v1 - mean) * inv * g[tid + 256] + b[tid + 256];
    out[(size_t)row * EE + tid]       = y0;
    out[(size_t)row * EE + tid + 256] = y1;
    __nv_bfloat16 h0 = __float2bfloat16(y0);
    __nv_bfloat16 h1 = __float2bfloat16(y1);
    ohi[(size_t)row * EE + tid]       = h0;
    ohi[(size_t)row * EE + tid + 256] = h1;
    olo[(size_t)row * EE + tid]       = __float2bfloat16(y0 - __bfloat162float(h0));
    olo[(size_t)row * EE + tid + 256] = __float2bfloat16(y1 - __bfloat162float(h1));
}

// ---------------- weight transpose + hi/lo split ----------------------------
__global__ __launch_bounds__(256) void wsplit_kernel(const float* __restrict__ W,
                                                     __nv_bfloat16* __restrict__ Thi,
                                                     __nv_bfloat16* __restrict__ Tlo,
                                                     int K, int N) {
    __shared__ float t[32][33];
    const int n0 = blockIdx.x * 32, k0 = blockIdx.y * 32;
    const int tx = threadIdx.x & 31, ty = threadIdx.x >> 5;
    #pragma unroll
    for (int i = ty; i < 32; i += 8)
        t[i][tx] = W[(size_t)(k0 + i) * N + n0 + tx];
    __syncthreads();
    #pragma unroll
    for (int i = ty; i < 32; i += 8) {
        float v = t[tx][i];
        __nv_bfloat16 h = __float2bfloat16(v);
        Thi[(size_t)(n0 + i) * K + k0 + tx] = h;
        Tlo[(size_t)(n0 + i) * K + k0 + tx] = __float2bfloat16(v - __bfloat162float(h));
    }
}

// W [H][E][D] -> T [H*D][E]
__global__ __launch_bounds__(256) void wsplit_qkv(const float* __restrict__ W,
                                                  __nv_bfloat16* __restrict__ Thi,
                                                  __nv_bfloat16* __restrict__ Tlo) {
    __shared__ float t[32][33];
    const int h = blockIdx.z;
    const int d0 = blockIdx.x * 32, e0 = blockIdx.y * 32;
    const int tx = threadIdx.x & 31, ty = threadIdx.x >> 5;
    const float* Wh = W + (size_t)h * EE * DD;
    #pragma unroll
    for (int i = ty; i < 32; i += 8)
        t[i][tx] = Wh[(size_t)(e0 + i) * DD + d0 + tx];
    __syncthreads();
    #pragma unroll
    for (int i = ty; i < 32; i += 8) {
        float v = t[tx][i];
        __nv_bfloat16 hh = __float2bfloat16(v);
        Thi[(size_t)(h * DD + d0 + i) * EE + e0 + tx] = hh;
        Tlo[(size_t)(h * DD + d0 + i) * EE + e0 + tx] =
            __float2bfloat16(v - __bfloat162float(hh));
    }
}

// ---------------- mma.sync flash attention -----------------------------------
// 64x64 tiles, 4 warps x 16 q-rows. S and PV on tensor cores, hi/lo split.
#define APAD 72
#define ATILE (64 * APAD)                 // halfwords per smem tile
__global__ __launch_bounds__(128) void attn_mma() {
    extern __shared__ __nv_bfloat16 asm_[];
    __nv_bfloat16* Qh = asm_;
    __nv_bfloat16* Ql = asm_ + ATILE;
    __nv_bfloat16* Kh = asm_ + 2 * ATILE;
    __nv_bfloat16* Kl = asm_ + 3 * ATILE;
    __nv_bfloat16* Vh = asm_ + 4 * ATILE;
    __nv_bfloat16* Vl = asm_ + 5 * ATILE;

    const int t0 = blockIdx.x * 64;
    const int bh = blockIdx.y, b = bh >> 3, h = bh & 7;
    const int tid = threadIdx.x, warp = tid >> 5, lane = tid & 31;

    const size_t qbase  = (size_t)(b * TT + t0) * EE + h * DD;
    const size_t kvbase = (size_t)b * TT * EE + h * DD;

    // load Q tile (64x64 hi/lo): 512 uint4 per tile, 128 thr x 4
    #pragma unroll
    for (int u = 0; u < 4; u++) {
        int unit = tid + u * 128;
        int r = unit >> 3, cq = unit & 7;
        size_t g = qbase + (size_t)r * EE + cq * 8;
        *(uint4*)&Qh[r * APAD + cq * 8] = *(const uint4*)&g_qhi[g];
        *(uint4*)&Ql[r * APAD + cq * 8] = *(const uint4*)&g_qlo[g];
    }

    const int r0 = warp * 16;
    const uint32_t aQh = smem_u32(&Qh[(r0 + (lane & 15)) * APAD + (lane >> 4) * 8]);
    const uint32_t aQl = smem_u32(&Ql[(r0 + (lane & 15)) * APAD + (lane >> 4) * 8]);
    const uint32_t aKh = smem_u32(&Kh[(lane & 7) * APAD + ((lane >> 3) & 1) * 8]);
    const uint32_t aKl = smem_u32(&Kl[(lane & 7) * APAD + ((lane >> 3) & 1) * 8]);
    const uint32_t aVh = smem_u32(&Vh[(lane & 15) * APAD]);
    const uint32_t aVl = smem_u32(&Vl[(lane & 15) * APAD]);

    float m0 = -1e30f, m1 = -1e30f, l0 = 0.f, l1 = 0.f;
    float o[8][4];
    #pragma unroll
    for (int n = 0; n < 8; n++)
        #pragma unroll
        for (int e = 0; e < 4; e++) o[n][e] = 0.f;

    const float scale = 0.022097086912079608f;   // 2048^-0.5
    const int ra = r0 + (lane >> 2);             // local q-row (second = ra+8)

    for (int s0 = 0; s0 <= t0; s0 += 64) {
        __syncthreads();
        #pragma unroll
        for (int u = 0; u < 4; u++) {
            int unit = tid + u * 128;
            int r = unit >> 3, cq = unit & 7;
            size_t g = kvbase + (size_t)(s0 + r) * EE + cq * 8;
            *(uint4*)&Kh[r * APAD + cq * 8] = *(const uint4*)&g_khi[g];
            *(uint4*)&Kl[r * APAD + cq * 8] = *(const uint4*)&g_klo[g];
            *(uint4*)&Vh[r * APAD + cq * 8] = *(const uint4*)&g_vhi[g];
            *(uint4*)&Vl[r * APAD + cq * 8] = *(const uint4*)&g_vlo[g];
        }
        __syncthreads();

        // ---- S = Q K^T (3 split passes) ----
        float c[8][4];
        #pragma unroll
        for (int n = 0; n < 8; n++)
            #pragma unroll
            for (int e = 0; e < 4; e++) c[n][e] = 0.f;
        #pragma unroll
        for (int kb = 0; kb < 4; kb++) {
            uint32_t qh[4], ql[4];
            ldm_x4(qh, aQh + kb * 32);
            ldm_x4(ql, aQl + kb * 32);
            #pragma unroll
            for (int n = 0; n < 8; n++) {
                uint32_t kh[2], kl[2];
                ldm_x2(kh, aKh + (uint32_t)(n * 8 * APAD * 2) + kb * 32);
                ldm_x2(kl, aKl + (uint32_t)(n * 8 * APAD * 2) + kb * 32);
                mma16816(c[n], qh, kh);
                mma16816(c[n], qh, kl);
                mma16816(c[n], ql, kh);
            }
        }

        // ---- causal mask (diagonal tile only) ----
        if (s0 == t0) {
            #pragma unroll
            for (int n = 0; n < 8; n++) {
                int c0 = 8 * n + 2 * (lane & 3);
                if (c0     > ra)     c[n][0] = -1e30f;
                if (c0 + 1 > ra)     c[n][1] = -1e30f;
                if (c0     > ra + 8) c[n][2] = -1e30f;
                if (c0 + 1 > ra + 8) c[n][3] = -1e30f;
            }
        }

        // ---- online softmax on fragments ----
        float tm0 = -1e30f, tm1 = -1e30f;
        #pragma unroll
        for (int n = 0; n < 8; n++) {
            tm0 = fmaxf(tm0, fmaxf(c[n][0], c[n][1]));
            tm1 = fmaxf(tm1, fmaxf(c[n][2], c[n][3]));
        }
        tm0 = fmaxf(tm0, __shfl_xor_sync(0xffffffffu, tm0, 1));
        tm0 = fmaxf(tm0, __shfl_xor_sync(0xffffffffu, tm0, 2));
        tm1 = fmaxf(tm1, __shfl_xor_sync(0xffffffffu, tm1, 1));
        tm1 = fmaxf(tm1, __shfl_xor_sync(0xffffffffu, tm1, 2));
        const float mn0 = fmaxf(m0, tm0 * scale);
        const float mn1 = fmaxf(m1, tm1 * scale);
        const float a0 = fexp(m0 - mn0);
        const float a1 = fexp(m1 - mn1);

        float rs0 = 0.f, rs1 = 0.f;
        uint32_t ph[4][4], pl[4][4];
        #pragma unroll
        for (int n = 0; n < 8; n++) {
            float p0 = fexp(fmaf(c[n][0], scale, -mn0));
            float p1 = fexp(fmaf(c[n][1], scale, -mn0));
            float p2 = fexp(fmaf(c[n][2], scale, -mn1));
            float p3 = fexp(fmaf(c[n][3], scale, -mn1));
            rs0 += p0 + p1;  rs1 += p2 + p3;
            __nv_bfloat162 hA, hB, lA, lB;
            hA.x = __float2bfloat16(p0); hA.y = __float2bfloat16(p1);
            hB.x = __float2bfloat16(p2); hB.y = __float2bfloat16(p3);
            lA.x = __float2bfloat16(p0 - __bfloat162float(hA.x));
            lA.y = __float2bfloat16(p1 - __bfloat162float(hA.y));
            lB.x = __float2bfloat16(p2 - __bfloat162float(hB.x));
            lB.y = __float2bfloat16(p3 - __bfloat162float(hB.y));
            const int t = n >> 1, half = (n & 1) * 2;   // a0/a1 (even n) or a2/a3 (odd n)
            ph[t][half + 0] = *(uint32_t*)&hA;
            ph[t][half + 1] = *(uint32_t*)&hB;
            pl[t][half + 0] = *(uint32_t*)&lA;
            pl[t][half + 1] = *(uint32_t*)&lB;
        }
        rs0 += __shfl_xor_sync(0xffffffffu, rs0, 1);
        rs0 += __shfl_xor_sync(0xffffffffu, rs0, 2);
        rs1 += __shfl_xor_sync(0xffffffffu, rs1, 1);
        rs1 += __shfl_xor_sync(0xffffffffu, rs1, 2);
        l0 = l0 * a0 + rs0;  l1 = l1 * a1 + rs1;
        m0 = mn0;  m1 = mn1;
        #pragma unroll
        for (int n = 0; n < 8; n++) {
            o[n][0] *= a0; o[n][1] *= a0; o[n][2] *= a1; o[n][3] *= a1;
        }

        // ---- O += P V (3 split passes; V via ldmatrix.trans) ----
        #pragma unroll
        for (int t = 0; t < 4; t++) {
            #pragma unroll
            for (int n = 0; n < 8; n++) {
                uint32_t vh[2], vl[2];
                ldm_x2t(vh, aVh + (uint32_t)(t * 16 * APAD * 2) + n * 16);
                ldm_x2t(vl, aVl + (uint32_t)(t * 16 * APAD * 2) + n * 16);
                mma16816(o[n], ph[t], vh);
                mma16816(o[n], pl[t], vh);
                mma16816(o[n], ph[t], vl);
            }
        }
    }

    // ---- epilogue: O/l -> bf16 hi/lo in [B,T,H*D] ----
    const float inv0 = 1.0f / l0, inv1 = 1.0f / l1;
    const size_t ob0 = (size_t)(b * TT + t0 + ra) * EE + h * DD + 2 * (lane & 3);
    const size_t ob1 = ob0 + (size_t)8 * EE;
    #pragma unroll
    for (int n = 0; n < 8; n++) {
        float y0 = o[n][0] * inv0, y1 = o[n][1] * inv0;
        float y2 = o[n][2] * inv1, y3 = o[n][3] * inv1;
        __nv_bfloat162 hh, ll;
        hh.x = __float2bfloat16(y0); hh.y = __float2bfloat16(y1);
        ll.x = __float2bfloat16(y0 - __bfloat162float(hh.x));
        ll.y = __float2bfloat16(y1 - __bfloat162float(hh.y));
        *(__nv_bfloat162*)&g_ohi[ob0 + 8 * n] = hh;
        *(__nv_bfloat162*)&g_olo[ob0 + 8 * n] = ll;
        hh.x = __float2bfloat16(y2); hh.y = __float2bfloat16(y3);
        ll.x = __float2bfloat16(y2 - __bfloat162float(hh.x));
        ll.y = __float2bfloat16(y3 - __bfloat162float(hh.y));
        *(__nv_bfloat162*)&g_ohi[ob1 + 8 * n] = hh;
        *(__nv_bfloat162*)&g_olo[ob1 + 8 * n] = ll;
    }
}

// ---------------- mma.sync split-bf16 GEMM, cp.async 2-stage -----------------
#define BKP 40
#define TILEB (128 * BKP * 2)
#define STAGEB (4 * TILEB)
template <int KK, bool HAS_BIAS, bool RELU, bool HAS_RES, bool OUTPAIR>
__global__ __launch_bounds__(256) void tc_gemm(
    const __nv_bfloat16* __restrict__ Ahi, const __nv_bfloat16* __restrict__ Alo,
    const __nv_bfloat16* __restrict__ Bhi, const __nv_bfloat16* __restrict__ Blo,
    const float* __restrict__ bias, const float* __restrict__ res,
    float* __restrict__ Cf, __nv_bfloat16* __restrict__ Chi, __nv_bfloat16* __restrict__ Clo,
    int Nc)
{
    extern __shared__ char smem[];
    const uint32_t sb = smem_u32(smem);
    const int tid = threadIdx.x;
    const int wid = tid >> 5, lane = tid & 31;
    const int wm = wid >> 2, wn = wid & 3;
    const int m0 = blockIdx.y * 128, n0 = blockIdx.x * 128;

    const __nv_bfloat16* Amh = Ahi + (size_t)m0 * KK;
    const __nv_bfloat16* Aml = Alo + (size_t)m0 * KK;
    const __nv_bfloat16* Bmh = Bhi + (size_t)n0 * KK;
    const __nv_bfloat16* Bml = Blo + (size_t)n0 * KK;

    const int prow0 = tid >> 2, pcq = tid & 3;
    const uint32_t poff0 = (uint32_t)(prow0 * BKP + pcq * 8) * 2;
    const uint32_t poff1 = (uint32_t)((prow0 + 64) * BKP + pcq * 8) * 2;

    const int arow = wm * 64 + (lane & 15), acol = (lane >> 4) * 8;
    const uint32_t oA = (uint32_t)(arow * BKP + acol) * 2;
    const int brow = wn * 32 + (lane & 7), bcol = ((lane >> 3) & 1) * 8;
    const uint32_t oB = (uint32_t)(brow * BKP + bcol) * 2;

    float c[4][4][4];
    #pragma unroll
    for (int i = 0; i < 4; i++)
        #pragma unroll
        for (int j = 0; j < 4; j++)
            #pragma unroll
            for (int e = 0; e < 4; e++) c[i][j][e] = 0.f;

    auto pf = [&](int kt, int st) {
        const int k0 = kt * 32;
        const uint32_t sbase = sb + (uint32_t)st * STAGEB;
        size_t g0 = (size_t)prow0 * KK + k0 + pcq * 8;
        size_t g1 = (size_t)(prow0 + 64) * KK + k0 + pcq * 8;
        cp16(sbase + poff0,             Amh + g0);
        cp16(sbase + poff1,             Amh + g1);
        cp16(sbase + TILEB + poff0,     Aml + g0);
        cp16(sbase + TILEB + poff1,     Aml + g1);
        cp16(sbase + 2 * TILEB + poff0, Bmh + g0);
        cp16(sbase + 2 * TILEB + poff1, Bmh + g1);
        cp16(sbase + 3 * TILEB + poff0, Bml + g0);
        cp16(sbase + 3 * TILEB + poff1, Bml + g1);
    };

    constexpr int NT = KK / 32;
    pf(0, 0);
    asm volatile("cp.async.commit_group;");
    for (int kt = 0; kt < NT; ++kt) {
        const int st = kt & 1;
        if (kt + 1 < NT) {
            pf(kt + 1, st ^ 1);
            asm volatile("cp.async.commit_group;");
            asm volatile("cp.async.wait_group 1;");
        } else {
            asm volatile("cp.async.wait_group 0;");
        }
        __syncthreads();
        const uint32_t sbase = sb + (uint32_t)st * STAGEB;
        #pragma unroll
        for (int ks = 0; ks < 2; ++ks) {
            const uint32_t koff = ks * 32;
            uint32_t ah[4][4], al[4][4], bh[4][2], bl[4][2];
            #pragma unroll
            for (int i = 0; i < 4; i++) {
                ldm_x4(ah[i], sbase + oA + (uint32_t)(i * 16 * BKP * 2) + koff);
                ldm_x4(al[i], sbase + TILEB + oA + (uint32_t)(i * 16 * BKP * 2) + koff);
            }
            #pragma unroll
            for (int j = 0; j < 4; j++) {
                ldm_x2(bh[j], sbase + 2 * TILEB + oB + (uint32_t)(j * 8 * BKP * 2) + koff);
                ldm_x2(bl[j], sbase + 3 * TILEB + oB + (uint32_t)(j * 8 * BKP * 2) + koff);
            }
            #pragma unroll
            for (int i = 0; i < 4; i++)
                #pragma unroll
                for (int j = 0; j < 4; j++) {
                    mma16816(c[i][j], ah[i], bh[j]);
                    mma16816(c[i][j], ah[i], bl[j]);
                    mma16816(c[i][j], al[i], bh[j]);
                }
        }
        __syncthreads();
    }

    const int er = m0 + wm * 64 + (lane >> 2);
    const int ec = n0 + wn * 32 + (lane & 3) * 2;
    #pragma unroll
    for (int i = 0; i < 4; i++) {
        #pragma unroll
        for (int rr = 0; rr < 2; rr++) {
            const int r = er + i * 16 + rr * 8;
            #pragma unroll
            for (int j = 0; j < 4; j++) {
                const int cc = ec + j * 8;
                float v0 = c[i][j][rr * 2 + 0];
                float v1 = c[i][j][rr * 2 + 1];
                if (HAS_BIAS) { v0 += bias[cc]; v1 += bias[cc + 1]; }
                if (RELU) { v0 = fmaxf(v0, 0.f); v1 = fmaxf(v1, 0.f); }
                if (HAS_RES) {
                    const float* rp = &res[(size_t)r * Nc + cc];
                    v0 += rp[0]; v1 += rp[1];
                }
                if (OUTPAIR) {
                    __nv_bfloat16 h0 = __float2bfloat16(v0), h1 = __float2bfloat16(v1);
                    __nv_bfloat162 hh; hh.x = h0; hh.y = h1;
                    __nv_bfloat162 ll;
                    ll.x = __float2bfloat16(v0 - __bfloat162float(h0));
                    ll.y = __float2bfloat16(v1 - __bfloat162float(h1));
                    *(__nv_bfloat162*)&Chi[(size_t)r * Nc + cc] = hh;
                    *(__nv_bfloat162*)&Clo[(size_t)r * Nc + cc] = ll;
                } else {
                    float2 ov = {v0, v1};
                    *(float2*)&Cf[(size_t)r * Nc + cc] = ov;
                }
            }
        }
    }
}

// ---------------- launch ----------------------------------------------------
extern "C" void kernel_launch(void* const* d_in, const int* in_sizes, int n_in,
                              void* d_out, int out_size) {
    const float* x   = (const float*)d_in[0];
    const float* Wq  = (const float*)d_in[1];
    const float* Wk  = (const float*)d_in[2];
    const float* Wv  = (const float*)d_in[3];
    const float* Wo  = (const float*)d_in[4];
    const float* bo  = (const float*)d_in[5];
    const float* W1  = (const float*)d_in[6];
    const float* b1  = (const float*)d_in[7];
    const float* W2  = (const float*)d_in[8];
    const float* b2  = (const float*)d_in[9];
    const float* g1  = (const float*)d_in[10];
    const float* be1 = (const float*)d_in[11];
    const float* g2  = (const float*)d_in[12];
    const float* be2 = (const float*)d_in[13];
    float* out = (float*)d_out;
    (void)in_sizes; (void)n_in; (void)out_size;

    float *xn, *x2, *xn2;
    __nv_bfloat16 *xnhi, *xnlo, *qhi, *qlo, *khi, *klo, *vhi, *vlo;
    __nv_bfloat16 *ohi, *olo, *x2hi, *x2lo, *h1hi, *h1lo;
    __nv_bfloat16 *wothi, *wotlo, *w1thi, *w1tlo, *w2thi, *w2tlo;
    __nv_bfloat16 *wqthi, *wqtlo, *wkthi, *wktlo, *wvthi, *wvtlo;
    cudaGetSymbolAddress((void**)&xn,   g_xn);
    cudaGetSymbolAddress((void**)&x2,   g_x2);
    cudaGetSymbolAddress((void**)&xn2,  g_xn2);
    cudaGetSymbolAddress((void**)&xnhi, g_xnhi);
    cudaGetSymbolAddress((void**)&xnlo, g_xnlo);
    cudaGetSymbolAddress((void**)&qhi,  g_qhi);
    cudaGetSymbolAddress((void**)&qlo,  g_qlo);
    cudaGetSymbolAddress((void**)&khi,  g_khi);
    cudaGetSymbolAddress((void**)&klo,  g_klo);
    cudaGetSymbolAddress((void**)&vhi,  g_vhi);
    cudaGetSymbolAddress((void**)&vlo,  g_vlo);
    cudaGetSymbolAddress((void**)&ohi,  g_ohi);
    cudaGetSymbolAddress((void**)&olo,  g_olo);
    cudaGetSymbolAddress((void**)&x2hi, g_x2hi);
    cudaGetSymbolAddress((void**)&x2lo, g_x2lo);
    cudaGetSymbolAddress((void**)&h1hi, g_h1hi);
    cudaGetSymbolAddress((void**)&h1lo, g_h1lo);
    cudaGetSymbolAddress((void**)&wothi, g_wothi);
    cudaGetSymbolAddress((void**)&wotlo, g_wotlo);
    cudaGetSymbolAddress((void**)&w1thi, g_w1thi);
    cudaGetSymbolAddress((void**)&w1tlo, g_w1tlo);
    cudaGetSymbolAddress((void**)&w2thi, g_w2thi);
    cudaGetSymbolAddress((void**)&w2tlo, g_w2tlo);
    cudaGetSymbolAddress((void**)&wqthi, g_wqthi);
    cudaGetSymbolAddress((void**)&wqtlo, g_wqtlo);
    cudaGetSymbolAddress((void**)&wkthi, g_wkthi);
    cudaGetSymbolAddress((void**)&wktlo, g_wktlo);
    cudaGetSymbolAddress((void**)&wvthi, g_wvthi);
    cudaGetSymbolAddress((void**)&wvtlo, g_wvtlo);

    const int attn_smem = 6 * ATILE * (int)sizeof(__nv_bfloat16);   // 55296 B
    cudaFuncSetAttribute(attn_mma,
                         cudaFuncAttributeMaxDynamicSharedMemorySize, attn_smem);
    const int tc_smem = 2 * STAGEB;                                 // 81920 B
    cudaFuncSetAttribute(tc_gemm<512, false, false, false, true>,
                         cudaFuncAttributeMaxDynamicSharedMemorySize, tc_smem);
    cudaFuncSetAttribute(tc_gemm<512, true, false, true, false>,
                         cudaFuncAttributeMaxDynamicSharedMemorySize, tc_smem);
    cudaFuncSetAttribute(tc_gemm<512, true, true, false, true>,
                         cudaFuncAttributeMaxDynamicSharedMemorySize, tc_smem);
    cudaFuncSetAttribute(tc_gemm<4096, true, false, true, false>,
                         cudaFuncAttributeMaxDynamicSharedMemorySize, tc_smem);

    // 0. weight prep
    wsplit_kernel<<<dim3(EE / 32, EE / 32), 256>>>(Wo, wothi, wotlo, EE, EE);
    wsplit_kernel<<<dim3(HIDD / 32, EE / 32), 256>>>(W1, w1thi, w1tlo, EE, HIDD);
    wsplit_kernel<<<dim3(EE / 32, HIDD / 32), 256>>>(W2, w2thi, w2tlo, HIDD, EE);
    wsplit_qkv<<<dim3(DD / 32, EE / 32, HH), 256>>>(Wq, wqthi, wqtlo);
    wsplit_qkv<<<dim3(DD / 32, EE / 32, HH), 256>>>(Wk, wkthi, wktlo);
    wsplit_qkv<<<dim3(DD / 32, EE / 32, HH), 256>>>(Wv, wvthi, wvtlo);
    // 1. xn = LN1(x)
    ln_kernel<<<NROWS, 256>>>(x, g1, be1, xn, xnhi, xnlo);
    // 2. q,k,v = xn @ W{q,k,v}  -> bf16 hi/lo [B,T,H*D]
    tc_gemm<512, false, false, false, true><<<dim3(EE / 128, NROWS / 128), 256, tc_smem>>>(
        xnhi, xnlo, wqthi, wqtlo, nullptr, nullptr, nullptr, qhi, qlo, EE);
    tc_gemm<512, false, false, false, true><<<dim3(EE / 128, NROWS / 128), 256, tc_smem>>>(
        xnhi, xnlo, wkthi, wktlo, nullptr, nullptr, nullptr, khi, klo, EE);
    tc_gemm<512, false, false, false, true><<<dim3(EE / 128, NROWS / 128), 256, tc_smem>>>(
        xnhi, xnlo, wvthi, wvtlo, nullptr, nullptr, nullptr, vhi, vlo, EE);
    // 3. causal attention (tensor cores) -> o hi/lo
    attn_mma<<<dim3(TT / 64, BB * HH), 128, attn_smem>>>();
    // 4. x2 = xn + o @ Wo + bo
    tc_gemm<512, true, false, true, false><<<dim3(EE / 128, NROWS / 128), 256, tc_smem>>>(
        ohi, olo, wothi, wotlo, bo, xn, x2, nullptr, nullptr, EE);
    // 5. xn2 = LN2(x2)
    ln_kernel<<<NROWS, 256>>>(x2, g2, be2, xn2, x2hi, x2lo);
    // 6. h1 = relu(xn2 @ W1 + b1)
    tc_gemm<512, true, true, false, true><<<dim3(HIDD / 128, NROWS / 128), 256, tc_smem>>>(
        x2hi, x2lo, w1thi, w1tlo, b1, nullptr, nullptr, h1hi, h1lo, HIDD);
    // 7. out = xn2 + h1 @ W2 + b2
    tc_gemm<4096, true, false, true, false><<<dim3(EE / 128, NROWS / 128), 256, tc_smem>>>(
        h1hi, h1lo, w2thi, w2tlo, b2, xn2, out, nullptr, nullptr, EE);
}